// round 3
// baseline (speedup 1.0000x reference)
#include <cuda_runtime.h>
#include <cuda_bf16.h>
#include <math.h>

// Problem dims (fixed by the reference)
#define BB   32
#define TT   512
#define DD   512
#define HH   8
#define DH   64
#define FFN  2048
#define NTOK (BB*TT)   // 16384

// ---------------------------------------------------------------------------
// Scratch (device globals; no allocations allowed)
// ---------------------------------------------------------------------------
__device__ float g_Q [NTOK*DD];
__device__ float g_K [NTOK*DD];
__device__ float g_V [NTOK*DD];
__device__ float g_AO[NTOK*DD];
__device__ float g_T [NTOK*DD];
__device__ float g_Y [NTOK*DD];
__device__ float g_Z [NTOK*DD];
__device__ float g_Hh[NTOK*FFN];

// ---------------------------------------------------------------------------
// SGEMM:  C[M,N] = A[M,K] * B[N,K]^T   (both operands K-major / row-major)
// EPI: 0 = none, 1 = +bias then LeakyReLU(0.01), 2 = +bias
// BM=BN=128, BK=16, 256 threads, 8x8 per thread.
// All dims here are multiples of the tiles (M=16384, N in {512,2048}, K in {512,2048}).
// ---------------------------------------------------------------------------
template<int EPI>
__global__ __launch_bounds__(256)
void sgemm_nt(const float* __restrict__ A, const float* __restrict__ B,
              const float* __restrict__ bias, float* __restrict__ C,
              int M, int N, int K)
{
    constexpr int BM = 128, BN = 128, BK = 16;
    __shared__ float As[BK][BM];
    __shared__ float Bs[BK][BN];

    const int bm  = blockIdx.y * BM;
    const int bn  = blockIdx.x * BN;
    const int tid = threadIdx.x;
    const int tx  = tid & 15;        // 0..15  (N dir)
    const int ty  = tid >> 4;        // 0..15  (M dir)

    float acc[8][8];
    #pragma unroll
    for (int i = 0; i < 8; i++)
        #pragma unroll
        for (int j = 0; j < 8; j++) acc[i][j] = 0.f;

    for (int k0 = 0; k0 < K; k0 += BK) {
        // load 128x16 tiles of A and B, store K-transposed into smem
        #pragma unroll
        for (int u = 0; u < 2; u++) {
            int f   = tid + u * 256;       // 0..511  (float4 index)
            int row = f >> 2;              // 0..127
            int c4  = (f & 3) * 4;         // 0,4,8,12
            float4 av = *(const float4*)(A + (size_t)(bm + row) * K + k0 + c4);
            As[c4 + 0][row] = av.x; As[c4 + 1][row] = av.y;
            As[c4 + 2][row] = av.z; As[c4 + 3][row] = av.w;
            float4 bv = *(const float4*)(B + (size_t)(bn + row) * K + k0 + c4);
            Bs[c4 + 0][row] = bv.x; Bs[c4 + 1][row] = bv.y;
            Bs[c4 + 2][row] = bv.z; Bs[c4 + 3][row] = bv.w;
        }
        __syncthreads();

        #pragma unroll
        for (int kk = 0; kk < BK; kk++) {
            float a[8], b[8];
            *(float4*)&a[0] = *(const float4*)&As[kk][ty * 8];
            *(float4*)&a[4] = *(const float4*)&As[kk][ty * 8 + 4];
            *(float4*)&b[0] = *(const float4*)&Bs[kk][tx * 8];
            *(float4*)&b[4] = *(const float4*)&Bs[kk][tx * 8 + 4];
            #pragma unroll
            for (int i = 0; i < 8; i++)
                #pragma unroll
                for (int j = 0; j < 8; j++)
                    acc[i][j] = fmaf(a[i], b[j], acc[i][j]);
        }
        __syncthreads();
    }

    // epilogue
    float bj[8];
    if (EPI) {
        #pragma unroll
        for (int j = 0; j < 8; j++) bj[j] = bias[bn + tx * 8 + j];
    }
    #pragma unroll
    for (int i = 0; i < 8; i++) {
        float* crow = C + (size_t)(bm + ty * 8 + i) * N + bn + tx * 8;
        #pragma unroll
        for (int j4 = 0; j4 < 2; j4++) {
            float4 v;
            v.x = acc[i][j4 * 4 + 0]; v.y = acc[i][j4 * 4 + 1];
            v.z = acc[i][j4 * 4 + 2]; v.w = acc[i][j4 * 4 + 3];
            if (EPI) {
                v.x += bj[j4 * 4 + 0]; v.y += bj[j4 * 4 + 1];
                v.z += bj[j4 * 4 + 2]; v.w += bj[j4 * 4 + 3];
                if (EPI == 1) {
                    v.x = v.x > 0.f ? v.x : 0.01f * v.x;
                    v.y = v.y > 0.f ? v.y : 0.01f * v.y;
                    v.z = v.z > 0.f ? v.z : 0.01f * v.z;
                    v.w = v.w > 0.f ? v.w : 0.01f * v.w;
                }
            }
            *(float4*)(crow + j4 * 4) = v;
        }
    }
}

// ---------------------------------------------------------------------------
// Fused attention (flash-style) for one (b,h,q-tile of 64).
// Q,K,V,O are [B*T, 512] with head h at columns h*64 .. h*64+63.
// per_query=1: valid = vlen[b*T + q]  (self-attn, [B,T])
// per_query=0: valid = vlen[b]        (cross-attn, [B])
// Early exit past the block's max valid length (exactly-zero contributions).
// Static smem = 48KB: Qs, Ks(reused as Ps), Vs.
// ---------------------------------------------------------------------------
__global__ __launch_bounds__(256)
void attn_kernel(const float* __restrict__ Q, const float* __restrict__ Kg,
                 const float* __restrict__ Vg, const int* __restrict__ vlen,
                 int per_query, float* __restrict__ O)
{
    __shared__ float Qs[64 * 64];
    __shared__ float KPs[64 * 64];   // K tile, reused for P after S-compute
    __shared__ float Vs[64 * 64];

    const int b  = blockIdx.z;
    const int h  = blockIdx.y;
    const int q0 = blockIdx.x * 64;
    const int tid = threadIdx.x;
    const int q  = tid >> 2;        // 0..63
    const int qu = tid & 3;         // 0..3 -> 16-wide slice
    const size_t rowbase = ((size_t)b * TT) * DD + h * DH;

    // load Q tile [64 q][64 d]
    #pragma unroll
    for (int u = 0; u < 4; u++) {
        int l = tid + u * 256;               // 0..1023 float4 slots
        int r = l >> 4, c4 = (l & 15) * 4;
        *(float4*)&Qs[r * 64 + c4] =
            *(const float4*)(Q + rowbase + (size_t)(q0 + r) * DD + c4);
    }

    const int vlq = per_query ? vlen[b * TT + q0 + q] : vlen[b];

    // block max valid length (for early exit)
    int v = vlq;
    #pragma unroll
    for (int off = 16; off; off >>= 1)
        v = max(v, __shfl_xor_sync(0xffffffffu, v, off));
    if ((tid & 31) == 0) ((int*)KPs)[tid >> 5] = v;
    __syncthreads();
    int maxvl = ((int*)KPs)[0];
    #pragma unroll
    for (int i = 1; i < 8; i++) maxvl = max(maxvl, ((int*)KPs)[i]);

    float m = -1e30f, lsum = 0.f;
    float o[16];
    #pragma unroll
    for (int i = 0; i < 16; i++) o[i] = 0.f;

    const int ktiles = (maxvl + 63) >> 6;    // <= 8

    for (int kt = 0; kt < ktiles; kt++) {
        const int k0g = kt * 64;
        __syncthreads();   // previous iteration's consumers done
        #pragma unroll
        for (int u = 0; u < 4; u++) {
            int l = tid + u * 256;
            int r = l >> 4, c4 = (l & 15) * 4;
            *(float4*)&KPs[r * 64 + c4] =
                *(const float4*)(Kg + rowbase + (size_t)(k0g + r) * DD + c4);
            *(float4*)&Vs[r * 64 + c4] =
                *(const float4*)(Vg + rowbase + (size_t)(k0g + r) * DD + c4);
        }
        __syncthreads();

        // S[q][k] for this thread's 16 k values (k = qu*16+j)
        float s[16];
        #pragma unroll
        for (int j = 0; j < 16; j++) s[j] = 0.f;
        #pragma unroll
        for (int d4 = 0; d4 < 16; d4++) {
            float4 qv = *(const float4*)&Qs[q * 64 + d4 * 4];
            #pragma unroll
            for (int j = 0; j < 16; j++) {
                float4 kv = *(const float4*)&KPs[(qu * 16 + j) * 64 + d4 * 4];
                s[j] += qv.x * kv.x + qv.y * kv.y + qv.z * kv.z + qv.w * kv.w;
            }
        }
        __syncthreads();   // everyone done reading K tile; KPs becomes P

        float tmax = -1e30f;
        #pragma unroll
        for (int j = 0; j < 16; j++) {
            s[j] *= 0.125f;                              // 1/sqrt(64)
            if (k0g + qu * 16 + j >= vlq) s[j] = -1e10f; // mask
            tmax = fmaxf(tmax, s[j]);
        }
        tmax = fmaxf(tmax, __shfl_xor_sync(0xffffffffu, tmax, 1));
        tmax = fmaxf(tmax, __shfl_xor_sync(0xffffffffu, tmax, 2));
        const float mn = fmaxf(m, tmax);
        const float alpha = expf(m - mn);

        float psum = 0.f;
        #pragma unroll
        for (int j = 0; j < 16; j++) {
            float p = expf(s[j] - mn);
            KPs[q * 64 + qu * 16 + j] = p;
            psum += p;
        }
        psum += __shfl_xor_sync(0xffffffffu, psum, 1);
        psum += __shfl_xor_sync(0xffffffffu, psum, 2);
        lsum = lsum * alpha + psum;
        m = mn;
        #pragma unroll
        for (int i = 0; i < 16; i++) o[i] *= alpha;
        __syncthreads();   // P visible to all

        // O[q][d] += sum_k P[q][k] * V[k][d]   (d = qu*16 .. +15)
        #pragma unroll
        for (int k = 0; k < 64; k++) {
            float p = KPs[q * 64 + k];
            #pragma unroll
            for (int i4 = 0; i4 < 4; i4++) {
                float4 vv = *(const float4*)&Vs[k * 64 + qu * 16 + i4 * 4];
                o[i4 * 4 + 0] = fmaf(p, vv.x, o[i4 * 4 + 0]);
                o[i4 * 4 + 1] = fmaf(p, vv.y, o[i4 * 4 + 1]);
                o[i4 * 4 + 2] = fmaf(p, vv.z, o[i4 * 4 + 2]);
                o[i4 * 4 + 3] = fmaf(p, vv.w, o[i4 * 4 + 3]);
            }
        }
    }

    const float inv = 1.f / lsum;
    float* dst = O + rowbase + (size_t)(q0 + q) * DD + qu * 16;
    #pragma unroll
    for (int i4 = 0; i4 < 4; i4++) {
        float4 w;
        w.x = o[i4 * 4 + 0] * inv; w.y = o[i4 * 4 + 1] * inv;
        w.z = o[i4 * 4 + 2] * inv; w.w = o[i4 * 4 + 3] * inv;
        *(float4*)(dst + i4 * 4) = w;
    }
}

// ---------------------------------------------------------------------------
// out[row] = LayerNorm(x[row] + y[row]) * gamma + beta, D = 512
// 128 threads/row, float4 per thread.
// ---------------------------------------------------------------------------
__global__ __launch_bounds__(128)
void add_ln_kernel(const float* __restrict__ x, const float* __restrict__ y,
                   const float* __restrict__ g, const float* __restrict__ be,
                   float* __restrict__ out)
{
    __shared__ float ws[4], ws2[4];
    const int row = blockIdx.x;
    const int tid = threadIdx.x;

    float4 xv = ((const float4*)(x + (size_t)row * DD))[tid];
    float4 yv = ((const float4*)(y + (size_t)row * DD))[tid];
    float4 v;
    v.x = xv.x + yv.x; v.y = xv.y + yv.y; v.z = xv.z + yv.z; v.w = xv.w + yv.w;

    float s  = v.x + v.y + v.z + v.w;
    float s2 = v.x * v.x + v.y * v.y + v.z * v.z + v.w * v.w;
    #pragma unroll
    for (int off = 16; off; off >>= 1) {
        s  += __shfl_xor_sync(0xffffffffu, s,  off);
        s2 += __shfl_xor_sync(0xffffffffu, s2, off);
    }
    if ((tid & 31) == 0) { ws[tid >> 5] = s; ws2[tid >> 5] = s2; }
    __syncthreads();
    s  = ws[0]  + ws[1]  + ws[2]  + ws[3];
    s2 = ws2[0] + ws2[1] + ws2[2] + ws2[3];

    const float mean = s * (1.f / DD);
    const float var  = s2 * (1.f / DD) - mean * mean;
    const float r    = rsqrtf(var + 1e-5f);

    float4 gv = ((const float4*)g)[tid];
    float4 bv = ((const float4*)be)[tid];
    float4 w;
    w.x = (v.x - mean) * r * gv.x + bv.x;
    w.y = (v.y - mean) * r * gv.y + bv.y;
    w.z = (v.z - mean) * r * gv.z + bv.z;
    w.w = (v.w - mean) * r * gv.w + bv.w;
    ((float4*)(out + (size_t)row * DD))[tid] = w;
}

// ---------------------------------------------------------------------------
// Host driver
// ---------------------------------------------------------------------------
static float* symaddr(const void* sym)
{
    void* p = nullptr;
    cudaGetSymbolAddress(&p, sym);
    return (float*)p;
}

extern "C" void kernel_launch(void* const* d_in, const int* in_sizes, int n_in,
                              void* d_out, int out_size)
{
    (void)in_sizes; (void)n_in; (void)out_size;

    const float* X    = (const float*)d_in[0];
    const float* enc  = (const float*)d_in[1];
    const int*   dvl  = (const int*)d_in[2];
    const int*   evl  = (const int*)d_in[3];
    const float* Wq1  = (const float*)d_in[4];
    const float* Wk1  = (const float*)d_in[5];
    const float* Wv1  = (const float*)d_in[6];
    const float* Wo1  = (const float*)d_in[7];
    const float* Wq2  = (const float*)d_in[8];
    const float* Wk2  = (const float*)d_in[9];
    const float* Wv2  = (const float*)d_in[10];
    const float* Wo2  = (const float*)d_in[11];
    const float* W1   = (const float*)d_in[12];
    const float* b1   = (const float*)d_in[13];
    const float* W2   = (const float*)d_in[14];
    const float* b2   = (const float*)d_in[15];
    const float* g1   = (const float*)d_in[16];
    const float* be1  = (const float*)d_in[17];
    const float* g2   = (const float*)d_in[18];
    const float* be2  = (const float*)d_in[19];
    const float* g3   = (const float*)d_in[20];
    const float* be3  = (const float*)d_in[21];
    float* out = (float*)d_out;

    float* Qb  = symaddr(g_Q);
    float* Kb  = symaddr(g_K);
    float* Vb  = symaddr(g_V);
    float* AOb = symaddr(g_AO);
    float* Tb  = symaddr(g_T);
    float* Yb  = symaddr(g_Y);
    float* Zb  = symaddr(g_Z);
    float* Hb  = symaddr(g_Hh);

    const int M = NTOK;
    dim3 gD(DD / 128, M / 128);     // N=512 GEMMs
    dim3 gF(FFN / 128, M / 128);    // N=2048 GEMM
    dim3 gA(TT / 64, HH, BB);       // attention

    // ---- self-attention ----
    sgemm_nt<0><<<gD, 256>>>(X, Wq1, nullptr, Qb, M, DD, DD);
    sgemm_nt<0><<<gD, 256>>>(X, Wk1, nullptr, Kb, M, DD, DD);
    sgemm_nt<0><<<gD, 256>>>(X, Wv1, nullptr, Vb, M, DD, DD);
    attn_kernel<<<gA, 256>>>(Qb, Kb, Vb, dvl, 1, AOb);
    sgemm_nt<0><<<gD, 256>>>(AOb, Wo1, nullptr, Tb, M, DD, DD);
    add_ln_kernel<<<M, 128>>>(X, Tb, g1, be1, Yb);

    // ---- cross-attention ----
    sgemm_nt<0><<<gD, 256>>>(Yb,  Wq2, nullptr, Qb, M, DD, DD);
    sgemm_nt<0><<<gD, 256>>>(enc, Wk2, nullptr, Kb, M, DD, DD);
    sgemm_nt<0><<<gD, 256>>>(enc, Wv2, nullptr, Vb, M, DD, DD);
    attn_kernel<<<gA, 256>>>(Qb, Kb, Vb, evl, 0, AOb);
    sgemm_nt<0><<<gD, 256>>>(AOb, Wo2, nullptr, Tb, M, DD, DD);
    add_ln_kernel<<<M, 128>>>(Yb, Tb, g2, be2, Zb);

    // ---- FFN ----
    sgemm_nt<1><<<gF, 256>>>(Zb, W1, b1, Hb, M, FFN, DD);   // + bias + LeakyReLU
    sgemm_nt<2><<<gD, 256>>>(Hb, W2, b2, Tb, M, DD, FFN);   // + bias
    add_ln_kernel<<<M, 128>>>(Zb, Tb, g3, be3, out);
}

// round 4
// speedup vs baseline: 1.3145x; 1.3145x over previous
#include <cuda_runtime.h>
#include <cuda_bf16.h>
#include <math.h>
#include <stdint.h>

// Problem dims (fixed by the reference)
#define BB   32
#define TT   512
#define DD   512
#define HH   8
#define DH   64
#define FFN  2048
#define NTOK (BB*TT)   // 16384

// ---------------------------------------------------------------------------
// Scratch (device globals; no allocations allowed)
// ---------------------------------------------------------------------------
__device__ float g_Q [NTOK*DD];
__device__ float g_K [NTOK*DD];
__device__ float g_V [NTOK*DD];
__device__ float g_AO[NTOK*DD];
__device__ float g_T [NTOK*DD];
__device__ float g_Y [NTOK*DD];
__device__ float g_Z [NTOK*DD];
__device__ float g_Hh[NTOK*FFN];

// ---------------------------------------------------------------------------
// PTX helpers
// ---------------------------------------------------------------------------
__device__ __forceinline__ uint32_t sptr(const void* p)
{
    return (uint32_t)__cvta_generic_to_shared(p);
}

__device__ __forceinline__ void ldsm_x4(uint32_t& r0, uint32_t& r1,
                                        uint32_t& r2, uint32_t& r3, uint32_t addr)
{
    asm volatile("ldmatrix.sync.aligned.m8n8.x4.shared.b16 {%0,%1,%2,%3}, [%4];"
                 : "=r"(r0), "=r"(r1), "=r"(r2), "=r"(r3) : "r"(addr));
}

__device__ __forceinline__ void mma_bf16(float* c, const uint32_t* a, const uint32_t* b)
{
    asm volatile("mma.sync.aligned.m16n8k16.row.col.f32.bf16.bf16.f32 "
                 "{%0,%1,%2,%3}, {%4,%5,%6,%7}, {%8,%9}, {%0,%1,%2,%3};"
                 : "+f"(c[0]), "+f"(c[1]), "+f"(c[2]), "+f"(c[3])
                 : "r"(a[0]), "r"(a[1]), "r"(a[2]), "r"(a[3]),
                   "r"(b[0]), "r"(b[1]));
}

// ---------------------------------------------------------------------------
// bf16x3 split tensor-core GEMM:
//   C[M,N] = A[M,K] * B[N,K]^T   in ~fp32 precision via
//   C = Ahi*Bhi + Ahi*Blo + Alo*Bhi  (hi = bf16(x), lo = bf16(x - hi))
// BM=BN=128, BK=32, 256 threads (8 warps, 2x4), warp tile 64x32.
// EPI: 0 none, 1 +bias+LeakyReLU(0.01), 2 +bias.
// All dims are multiples of the tiles.
// ---------------------------------------------------------------------------
template<int EPI>
__global__ __launch_bounds__(256)
void bgemm_nt(const float* __restrict__ A, const float* __restrict__ B,
              const float* __restrict__ bias, float* __restrict__ C,
              int M, int N, int K)
{
    constexpr int BM = 128, BN = 128, BK = 32, LD = 40;  // LD: bf16 row pitch (80B)
    __shared__ __align__(16) __nv_bfloat16 Ah[BM * LD];
    __shared__ __align__(16) __nv_bfloat16 Al[BM * LD];
    __shared__ __align__(16) __nv_bfloat16 Bh[BN * LD];
    __shared__ __align__(16) __nv_bfloat16 Bl[BN * LD];

    const int bm   = blockIdx.y * BM;
    const int bn   = blockIdx.x * BN;
    const int tid  = threadIdx.x;
    const int lane = tid & 31;
    const int wid  = tid >> 5;
    const int wm   = wid >> 2;   // 0..1 -> 64 rows
    const int wn   = wid & 3;    // 0..3 -> 32 cols

    float acc[4][4][4];
    #pragma unroll
    for (int i = 0; i < 4; i++)
        #pragma unroll
        for (int j = 0; j < 4; j++)
            #pragma unroll
            for (int t = 0; t < 4; t++) acc[i][j][t] = 0.f;

    // ldmatrix source-row mapping (per lane)
    const int arow = ((lane >> 3) & 1) * 8 + (lane & 7);   // A tiles: rows0-7,rows8-15 (k0-7) then same (k8-15)
    const int acol = ((lane >> 4) & 1) * 8;
    const int brow = ((lane >> 4) & 1) * 8 + (lane & 7);   // B tiles: n0-7 (k0-7,k8-15) then n8-15
    const int bcol = ((lane >> 3) & 1) * 8;

    for (int k0 = 0; k0 < K; k0 += BK) {
        __syncthreads();
        // stage & split A,B tiles: 128 rows x 32 cols fp32 each
        #pragma unroll
        for (int u = 0; u < 4; u++) {
            int idx = tid + u * 256;        // 0..1023 float4 slots
            int row = idx >> 3;
            int c4  = (idx & 7) * 4;
            {
                float4 v = *(const float4*)(A + (size_t)(bm + row) * K + k0 + c4);
                __nv_bfloat16 hx = __float2bfloat16(v.x), hy = __float2bfloat16(v.y);
                __nv_bfloat16 hz = __float2bfloat16(v.z), hw = __float2bfloat16(v.w);
                __nv_bfloat16 lx = __float2bfloat16(v.x - __bfloat162float(hx));
                __nv_bfloat16 ly = __float2bfloat16(v.y - __bfloat162float(hy));
                __nv_bfloat16 lz = __float2bfloat16(v.z - __bfloat162float(hz));
                __nv_bfloat16 lw = __float2bfloat16(v.w - __bfloat162float(hw));
                *(__nv_bfloat162*)&Ah[row * LD + c4]     = __halves2bfloat162(hx, hy);
                *(__nv_bfloat162*)&Ah[row * LD + c4 + 2] = __halves2bfloat162(hz, hw);
                *(__nv_bfloat162*)&Al[row * LD + c4]     = __halves2bfloat162(lx, ly);
                *(__nv_bfloat162*)&Al[row * LD + c4 + 2] = __halves2bfloat162(lz, lw);
            }
            {
                float4 v = *(const float4*)(B + (size_t)(bn + row) * K + k0 + c4);
                __nv_bfloat16 hx = __float2bfloat16(v.x), hy = __float2bfloat16(v.y);
                __nv_bfloat16 hz = __float2bfloat16(v.z), hw = __float2bfloat16(v.w);
                __nv_bfloat16 lx = __float2bfloat16(v.x - __bfloat162float(hx));
                __nv_bfloat16 ly = __float2bfloat16(v.y - __bfloat162float(hy));
                __nv_bfloat16 lz = __float2bfloat16(v.z - __bfloat162float(hz));
                __nv_bfloat16 lw = __float2bfloat16(v.w - __bfloat162float(hw));
                *(__nv_bfloat162*)&Bh[row * LD + c4]     = __halves2bfloat162(hx, hy);
                *(__nv_bfloat162*)&Bh[row * LD + c4 + 2] = __halves2bfloat162(hz, hw);
                *(__nv_bfloat162*)&Bl[row * LD + c4]     = __halves2bfloat162(lx, ly);
                *(__nv_bfloat162*)&Bl[row * LD + c4 + 2] = __halves2bfloat162(lz, lw);
            }
        }
        __syncthreads();

        #pragma unroll
        for (int kk = 0; kk < BK; kk += 16) {
            uint32_t ah[4][4], al[4][4], bh[4][2], bl[4][2];
            #pragma unroll
            for (int mf = 0; mf < 4; mf++) {
                int r = wm * 64 + mf * 16 + arow;
                ldsm_x4(ah[mf][0], ah[mf][1], ah[mf][2], ah[mf][3],
                        sptr(&Ah[r * LD + kk + acol]));
                ldsm_x4(al[mf][0], al[mf][1], al[mf][2], al[mf][3],
                        sptr(&Al[r * LD + kk + acol]));
            }
            #pragma unroll
            for (int p = 0; p < 2; p++) {
                int n = wn * 32 + p * 16 + brow;
                uint32_t t0, t1, t2, t3;
                ldsm_x4(t0, t1, t2, t3, sptr(&Bh[n * LD + kk + bcol]));
                bh[2 * p][0] = t0; bh[2 * p][1] = t1;
                bh[2 * p + 1][0] = t2; bh[2 * p + 1][1] = t3;
                ldsm_x4(t0, t1, t2, t3, sptr(&Bl[n * LD + kk + bcol]));
                bl[2 * p][0] = t0; bl[2 * p][1] = t1;
                bl[2 * p + 1][0] = t2; bl[2 * p + 1][1] = t3;
            }
            #pragma unroll
            for (int mf = 0; mf < 4; mf++)
                #pragma unroll
                for (int nf = 0; nf < 4; nf++)
                    mma_bf16(acc[mf][nf], ah[mf], bh[nf]);
            #pragma unroll
            for (int mf = 0; mf < 4; mf++)
                #pragma unroll
                for (int nf = 0; nf < 4; nf++)
                    mma_bf16(acc[mf][nf], ah[mf], bl[nf]);
            #pragma unroll
            for (int mf = 0; mf < 4; mf++)
                #pragma unroll
                for (int nf = 0; nf < 4; nf++)
                    mma_bf16(acc[mf][nf], al[mf], bh[nf]);
        }
    }

    // epilogue: C fragment lane mapping: c0,c1 -> (r, c), (r, c+1); c2,c3 -> (r+8, ...)
    const int r0  = lane >> 2;
    const int cc0 = (lane & 3) * 2;
    #pragma unroll
    for (int mf = 0; mf < 4; mf++) {
        #pragma unroll
        for (int nf = 0; nf < 4; nf++) {
            int row = bm + wm * 64 + mf * 16 + r0;
            int col = bn + wn * 32 + nf * 8 + cc0;
            float2 v0 = make_float2(acc[mf][nf][0], acc[mf][nf][1]);
            float2 v1 = make_float2(acc[mf][nf][2], acc[mf][nf][3]);
            if (EPI) {
                float b0 = bias[col], b1 = bias[col + 1];
                v0.x += b0; v0.y += b1; v1.x += b0; v1.y += b1;
                if (EPI == 1) {
                    v0.x = v0.x > 0.f ? v0.x : 0.01f * v0.x;
                    v0.y = v0.y > 0.f ? v0.y : 0.01f * v0.y;
                    v1.x = v1.x > 0.f ? v1.x : 0.01f * v1.x;
                    v1.y = v1.y > 0.f ? v1.y : 0.01f * v1.y;
                }
            }
            *(float2*)(C + (size_t)row * N + col)       = v0;
            *(float2*)(C + (size_t)(row + 8) * N + col) = v1;
        }
    }
}

// ---------------------------------------------------------------------------
// Fused attention (flash-style), unchanged from R1 (fp32).
// ---------------------------------------------------------------------------
__global__ __launch_bounds__(256)
void attn_kernel(const float* __restrict__ Q, const float* __restrict__ Kg,
                 const float* __restrict__ Vg, const int* __restrict__ vlen,
                 int per_query, float* __restrict__ O)
{
    __shared__ float Qs[64 * 64];
    __shared__ float KPs[64 * 64];
    __shared__ float Vs[64 * 64];

    const int b  = blockIdx.z;
    const int h  = blockIdx.y;
    const int q0 = blockIdx.x * 64;
    const int tid = threadIdx.x;
    const int q  = tid >> 2;
    const int qu = tid & 3;
    const size_t rowbase = ((size_t)b * TT) * DD + h * DH;

    #pragma unroll
    for (int u = 0; u < 4; u++) {
        int l = tid + u * 256;
        int r = l >> 4, c4 = (l & 15) * 4;
        *(float4*)&Qs[r * 64 + c4] =
            *(const float4*)(Q + rowbase + (size_t)(q0 + r) * DD + c4);
    }

    const int vlq = per_query ? vlen[b * TT + q0 + q] : vlen[b];

    int v = vlq;
    #pragma unroll
    for (int off = 16; off; off >>= 1)
        v = max(v, __shfl_xor_sync(0xffffffffu, v, off));
    if ((tid & 31) == 0) ((int*)KPs)[tid >> 5] = v;
    __syncthreads();
    int maxvl = ((int*)KPs)[0];
    #pragma unroll
    for (int i = 1; i < 8; i++) maxvl = max(maxvl, ((int*)KPs)[i]);

    float m = -1e30f, lsum = 0.f;
    float o[16];
    #pragma unroll
    for (int i = 0; i < 16; i++) o[i] = 0.f;

    const int ktiles = (maxvl + 63) >> 6;

    for (int kt = 0; kt < ktiles; kt++) {
        const int k0g = kt * 64;
        __syncthreads();
        #pragma unroll
        for (int u = 0; u < 4; u++) {
            int l = tid + u * 256;
            int r = l >> 4, c4 = (l & 15) * 4;
            *(float4*)&KPs[r * 64 + c4] =
                *(const float4*)(Kg + rowbase + (size_t)(k0g + r) * DD + c4);
            *(float4*)&Vs[r * 64 + c4] =
                *(const float4*)(Vg + rowbase + (size_t)(k0g + r) * DD + c4);
        }
        __syncthreads();

        float s[16];
        #pragma unroll
        for (int j = 0; j < 16; j++) s[j] = 0.f;
        #pragma unroll
        for (int d4 = 0; d4 < 16; d4++) {
            float4 qv = *(const float4*)&Qs[q * 64 + d4 * 4];
            #pragma unroll
            for (int j = 0; j < 16; j++) {
                float4 kv = *(const float4*)&KPs[(qu * 16 + j) * 64 + d4 * 4];
                s[j] += qv.x * kv.x + qv.y * kv.y + qv.z * kv.z + qv.w * kv.w;
            }
        }
        __syncthreads();

        float tmax = -1e30f;
        #pragma unroll
        for (int j = 0; j < 16; j++) {
            s[j] *= 0.125f;
            if (k0g + qu * 16 + j >= vlq) s[j] = -1e10f;
            tmax = fmaxf(tmax, s[j]);
        }
        tmax = fmaxf(tmax, __shfl_xor_sync(0xffffffffu, tmax, 1));
        tmax = fmaxf(tmax, __shfl_xor_sync(0xffffffffu, tmax, 2));
        const float mn = fmaxf(m, tmax);
        const float alpha = expf(m - mn);

        float psum = 0.f;
        #pragma unroll
        for (int j = 0; j < 16; j++) {
            float p = expf(s[j] - mn);
            KPs[q * 64 + qu * 16 + j] = p;
            psum += p;
        }
        psum += __shfl_xor_sync(0xffffffffu, psum, 1);
        psum += __shfl_xor_sync(0xffffffffu, psum, 2);
        lsum = lsum * alpha + psum;
        m = mn;
        #pragma unroll
        for (int i = 0; i < 16; i++) o[i] *= alpha;
        __syncthreads();

        #pragma unroll
        for (int k = 0; k < 64; k++) {
            float p = KPs[q * 64 + k];
            #pragma unroll
            for (int i4 = 0; i4 < 4; i4++) {
                float4 vv = *(const float4*)&Vs[k * 64 + qu * 16 + i4 * 4];
                o[i4 * 4 + 0] = fmaf(p, vv.x, o[i4 * 4 + 0]);
                o[i4 * 4 + 1] = fmaf(p, vv.y, o[i4 * 4 + 1]);
                o[i4 * 4 + 2] = fmaf(p, vv.z, o[i4 * 4 + 2]);
                o[i4 * 4 + 3] = fmaf(p, vv.w, o[i4 * 4 + 3]);
            }
        }
    }

    const float inv = 1.f / lsum;
    float* dst = O + rowbase + (size_t)(q0 + q) * DD + qu * 16;
    #pragma unroll
    for (int i4 = 0; i4 < 4; i4++) {
        float4 w;
        w.x = o[i4 * 4 + 0] * inv; w.y = o[i4 * 4 + 1] * inv;
        w.z = o[i4 * 4 + 2] * inv; w.w = o[i4 * 4 + 3] * inv;
        *(float4*)(dst + i4 * 4) = w;
    }
}

// ---------------------------------------------------------------------------
// out[row] = LayerNorm(x[row] + y[row]) * gamma + beta, D = 512
// ---------------------------------------------------------------------------
__global__ __launch_bounds__(128)
void add_ln_kernel(const float* __restrict__ x, const float* __restrict__ y,
                   const float* __restrict__ g, const float* __restrict__ be,
                   float* __restrict__ out)
{
    __shared__ float ws[4], ws2[4];
    const int row = blockIdx.x;
    const int tid = threadIdx.x;

    float4 xv = ((const float4*)(x + (size_t)row * DD))[tid];
    float4 yv = ((const float4*)(y + (size_t)row * DD))[tid];
    float4 v;
    v.x = xv.x + yv.x; v.y = xv.y + yv.y; v.z = xv.z + yv.z; v.w = xv.w + yv.w;

    float s  = v.x + v.y + v.z + v.w;
    float s2 = v.x * v.x + v.y * v.y + v.z * v.z + v.w * v.w;
    #pragma unroll
    for (int off = 16; off; off >>= 1) {
        s  += __shfl_xor_sync(0xffffffffu, s,  off);
        s2 += __shfl_xor_sync(0xffffffffu, s2, off);
    }
    if ((tid & 31) == 0) { ws[tid >> 5] = s; ws2[tid >> 5] = s2; }
    __syncthreads();
    s  = ws[0]  + ws[1]  + ws[2]  + ws[3];
    s2 = ws2[0] + ws2[1] + ws2[2] + ws2[3];

    const float mean = s * (1.f / DD);
    const float var  = s2 * (1.f / DD) - mean * mean;
    const float r    = rsqrtf(var + 1e-5f);

    float4 gv = ((const float4*)g)[tid];
    float4 bv = ((const float4*)be)[tid];
    float4 w;
    w.x = (v.x - mean) * r * gv.x + bv.x;
    w.y = (v.y - mean) * r * gv.y + bv.y;
    w.z = (v.z - mean) * r * gv.z + bv.z;
    w.w = (v.w - mean) * r * gv.w + bv.w;
    ((float4*)(out + (size_t)row * DD))[tid] = w;
}

// ---------------------------------------------------------------------------
// Host driver
// ---------------------------------------------------------------------------
static float* symaddr(const void* sym)
{
    void* p = nullptr;
    cudaGetSymbolAddress(&p, sym);
    return (float*)p;
}

extern "C" void kernel_launch(void* const* d_in, const int* in_sizes, int n_in,
                              void* d_out, int out_size)
{
    (void)in_sizes; (void)n_in; (void)out_size;

    const float* X    = (const float*)d_in[0];
    const float* enc  = (const float*)d_in[1];
    const int*   dvl  = (const int*)d_in[2];
    const int*   evl  = (const int*)d_in[3];
    const float* Wq1  = (const float*)d_in[4];
    const float* Wk1  = (const float*)d_in[5];
    const float* Wv1  = (const float*)d_in[6];
    const float* Wo1  = (const float*)d_in[7];
    const float* Wq2  = (const float*)d_in[8];
    const float* Wk2  = (const float*)d_in[9];
    const float* Wv2  = (const float*)d_in[10];
    const float* Wo2  = (const float*)d_in[11];
    const float* W1   = (const float*)d_in[12];
    const float* b1   = (const float*)d_in[13];
    const float* W2   = (const float*)d_in[14];
    const float* b2   = (const float*)d_in[15];
    const float* g1   = (const float*)d_in[16];
    const float* be1  = (const float*)d_in[17];
    const float* g2   = (const float*)d_in[18];
    const float* be2  = (const float*)d_in[19];
    const float* g3   = (const float*)d_in[20];
    const float* be3  = (const float*)d_in[21];
    float* out = (float*)d_out;

    float* Qb  = symaddr(g_Q);
    float* Kb  = symaddr(g_K);
    float* Vb  = symaddr(g_V);
    float* AOb = symaddr(g_AO);
    float* Tb  = symaddr(g_T);
    float* Yb  = symaddr(g_Y);
    float* Zb  = symaddr(g_Z);
    float* Hb  = symaddr(g_Hh);

    const int M = NTOK;
    dim3 gD(DD / 128, M / 128);     // N=512 GEMMs
    dim3 gF(FFN / 128, M / 128);    // N=2048 GEMM
    dim3 gA(TT / 64, HH, BB);       // attention

    // ---- self-attention ----
    bgemm_nt<0><<<gD, 256>>>(X, Wq1, nullptr, Qb, M, DD, DD);
    bgemm_nt<0><<<gD, 256>>>(X, Wk1, nullptr, Kb, M, DD, DD);
    bgemm_nt<0><<<gD, 256>>>(X, Wv1, nullptr, Vb, M, DD, DD);
    attn_kernel<<<gA, 256>>>(Qb, Kb, Vb, dvl, 1, AOb);
    bgemm_nt<0><<<gD, 256>>>(AOb, Wo1, nullptr, Tb, M, DD, DD);
    add_ln_kernel<<<M, 128>>>(X, Tb, g1, be1, Yb);

    // ---- cross-attention ----
    bgemm_nt<0><<<gD, 256>>>(Yb,  Wq2, nullptr, Qb, M, DD, DD);
    bgemm_nt<0><<<gD, 256>>>(enc, Wk2, nullptr, Kb, M, DD, DD);
    bgemm_nt<0><<<gD, 256>>>(enc, Wv2, nullptr, Vb, M, DD, DD);
    attn_kernel<<<gA, 256>>>(Qb, Kb, Vb, evl, 0, AOb);
    bgemm_nt<0><<<gD, 256>>>(AOb, Wo2, nullptr, Tb, M, DD, DD);
    add_ln_kernel<<<M, 128>>>(Yb, Tb, g2, be2, Zb);

    // ---- FFN ----
    bgemm_nt<1><<<gF, 256>>>(Zb, W1, b1, Hb, M, FFN, DD);   // + bias + LeakyReLU
    bgemm_nt<2><<<gD, 256>>>(Hb, W2, b2, Tb, M, DD, FFN);   // + bias
    add_ln_kernel<<<M, 128>>>(Zb, Tb, g3, be3, out);
}

// round 5
// speedup vs baseline: 1.4030x; 1.0673x over previous
#include <cuda_runtime.h>
#include <cuda_bf16.h>
#include <math.h>
#include <stdint.h>

// Problem dims (fixed by the reference)
#define BB   32
#define TT   512
#define DD   512
#define HH   8
#define DH   64
#define FFN  2048
#define NTOK (BB*TT)   // 16384

typedef __nv_bfloat16 bf16;
typedef __nv_bfloat162 bf162;

// ---------------------------------------------------------------------------
// Scratch (device globals; no allocations allowed)
// ---------------------------------------------------------------------------
// fp32
__device__ float g_Q [NTOK*DD];
__device__ float g_K [NTOK*DD];
__device__ float g_V [NTOK*DD];
__device__ float g_T [NTOK*DD];
__device__ float g_Y [NTOK*DD];
__device__ float g_Z [NTOK*DD];
// bf16 hi/lo split activations
__device__ bf16 g_Xh [NTOK*DD];
__device__ bf16 g_Xl [NTOK*DD];
__device__ bf16 g_Eh [NTOK*DD];
__device__ bf16 g_El [NTOK*DD];
__device__ bf16 g_Yh [NTOK*DD];
__device__ bf16 g_Yl [NTOK*DD];
__device__ bf16 g_Zh [NTOK*DD];
__device__ bf16 g_Zl [NTOK*DD];
__device__ bf16 g_AOh[NTOK*DD];
__device__ bf16 g_AOl[NTOK*DD];
__device__ bf16 g_Hh [NTOK*FFN];
__device__ bf16 g_Hl [NTOK*FFN];
// bf16 hi/lo split weights
__device__ bf16 g_Wh [8*DD*DD];
__device__ bf16 g_Wl [8*DD*DD];
__device__ bf16 g_W1h[FFN*DD];
__device__ bf16 g_W1l[FFN*DD];
__device__ bf16 g_W2h[DD*FFN];
__device__ bf16 g_W2l[DD*FFN];

// ---------------------------------------------------------------------------
// PTX helpers
// ---------------------------------------------------------------------------
__device__ __forceinline__ uint32_t sptr(const void* p)
{
    return (uint32_t)__cvta_generic_to_shared(p);
}

__device__ __forceinline__ void ldsm_x4(uint32_t& r0, uint32_t& r1,
                                        uint32_t& r2, uint32_t& r3, uint32_t addr)
{
    asm volatile("ldmatrix.sync.aligned.m8n8.x4.shared.b16 {%0,%1,%2,%3}, [%4];"
                 : "=r"(r0), "=r"(r1), "=r"(r2), "=r"(r3) : "r"(addr));
}

__device__ __forceinline__ void mma_bf16(float* c, const uint32_t* a, const uint32_t* b)
{
    asm volatile("mma.sync.aligned.m16n8k16.row.col.f32.bf16.bf16.f32 "
                 "{%0,%1,%2,%3}, {%4,%5,%6,%7}, {%8,%9}, {%0,%1,%2,%3};"
                 : "+f"(c[0]), "+f"(c[1]), "+f"(c[2]), "+f"(c[3])
                 : "r"(a[0]), "r"(a[1]), "r"(a[2]), "r"(a[3]),
                   "r"(b[0]), "r"(b[1]));
}

__device__ __forceinline__ void cp_async16(uint32_t saddr, const void* gaddr)
{
    asm volatile("cp.async.cg.shared.global [%0], [%1], 16;" :: "r"(saddr), "l"(gaddr));
}
__device__ __forceinline__ void cp_commit()
{
    asm volatile("cp.async.commit_group;");
}
template<int N>
__device__ __forceinline__ void cp_wait()
{
    asm volatile("cp.async.wait_group %0;" :: "n"(N));
}

__device__ __forceinline__ void split1(float v, bf16& h, bf16& l)
{
    h = __float2bfloat16(v);
    l = __float2bfloat16(v - __bfloat162float(h));
}

// ---------------------------------------------------------------------------
// split_kernel: fp32 x -> bf16 hi/lo, float4-vectorized
// ---------------------------------------------------------------------------
__global__ __launch_bounds__(256)
void split_kernel(const float* __restrict__ x, bf16* __restrict__ h,
                  bf16* __restrict__ l, int n4)
{
    int i = blockIdx.x * 256 + threadIdx.x;
    if (i >= n4) return;
    float4 v = ((const float4*)x)[i];
    bf16 hx, hy, hz, hw, lx, ly, lz, lw;
    split1(v.x, hx, lx); split1(v.y, hy, ly);
    split1(v.z, hz, lz); split1(v.w, hw, lw);
    ((bf162*)h)[i * 2]     = __halves2bfloat162(hx, hy);
    ((bf162*)h)[i * 2 + 1] = __halves2bfloat162(hz, hw);
    ((bf162*)l)[i * 2]     = __halves2bfloat162(lx, ly);
    ((bf162*)l)[i * 2 + 1] = __halves2bfloat162(lz, lw);
}

// ---------------------------------------------------------------------------
// bf16x3 split tensor-core GEMM, pre-split operands, cp.async double buffer.
//   C[M,N] = A[M,K] * B[N,K]^T ~ fp32
// BM=BN=128, BK=64, 256 threads (8 warps 2x4), warp tile 64x32.
// Smem per stage: 4 tiles (Ah,Al,Bh,Bl) of 128x64 bf16, 128B rows with XOR
// swizzle (chunk c ^ (row&7)) -> conflict-free ldmatrix. 2 stages = 128KB.
// EPI: 0 none, 1 +bias+LeakyReLU, 2 +bias.  OUT: 0 fp32 C, 1 split bf16 Ch/Cl.
// ---------------------------------------------------------------------------
template<int EPI, int OUT>
__global__ __launch_bounds__(256)
void bgemm2(const bf16* __restrict__ Ahg, const bf16* __restrict__ Alg,
            const bf16* __restrict__ Bhg, const bf16* __restrict__ Blg,
            const float* __restrict__ bias,
            float* __restrict__ C, bf16* __restrict__ Ch, bf16* __restrict__ Cl,
            int M, int N, int K)
{
    extern __shared__ bf16 smp[];
    constexpr int TILE = 128 * 64;          // elems per tile
    constexpr int STAGE = 4 * TILE;         // elems per stage

    const int bm   = blockIdx.y * 128;
    const int bn   = blockIdx.x * 128;
    const int tid  = threadIdx.x;
    const int lane = tid & 31;
    const int wid  = tid >> 5;
    const int wm   = wid >> 2;   // 0..1
    const int wn   = wid & 3;    // 0..3

    float acc[4][4][4];
    #pragma unroll
    for (int i = 0; i < 4; i++)
        #pragma unroll
        for (int j = 0; j < 4; j++)
            #pragma unroll
            for (int t = 0; t < 4; t++) acc[i][j][t] = 0.f;

    // ldmatrix lane mapping (validated in R3/R4)
    const int arow = ((lane >> 3) & 1) * 8 + (lane & 7);
    const int acol = ((lane >> 4) & 1) * 8;
    const int brow = ((lane >> 4) & 1) * 8 + (lane & 7);
    const int bcol = ((lane >> 3) & 1) * 8;

    // stage loader: 4096 16B chunks, 16 per thread
    auto load_stage = [&](int s, int k0) {
        bf16* base = smp + s * STAGE;
        #pragma unroll
        for (int t = 0; t < 4; t++) {
            int idx = tid + t * 256;          // 0..1023
            int row = idx >> 3, c = idx & 7;
            int soff = row * 64 + ((c ^ (row & 7)) << 3);
            cp_async16(sptr(base + soff),
                       Ahg + (size_t)(bm + row) * K + k0 + c * 8);
            cp_async16(sptr(base + TILE + soff),
                       Alg + (size_t)(bm + row) * K + k0 + c * 8);
            cp_async16(sptr(base + 2 * TILE + soff),
                       Bhg + (size_t)(bn + row) * K + k0 + c * 8);
            cp_async16(sptr(base + 3 * TILE + soff),
                       Blg + (size_t)(bn + row) * K + k0 + c * 8);
        }
    };

    auto compute_stage = [&](int s) {
        bf16* base = smp + s * STAGE;
        #pragma unroll
        for (int kk = 0; kk < 64; kk += 16) {
            uint32_t ah[4][4], al[4][4], bh[4][2], bl[4][2];
            #pragma unroll
            for (int mf = 0; mf < 4; mf++) {
                int r = wm * 64 + mf * 16 + arow;
                int c = (kk + acol) >> 3;
                int off = r * 64 + ((c ^ (r & 7)) << 3);
                ldsm_x4(ah[mf][0], ah[mf][1], ah[mf][2], ah[mf][3],
                        sptr(base + off));
                ldsm_x4(al[mf][0], al[mf][1], al[mf][2], al[mf][3],
                        sptr(base + TILE + off));
            }
            #pragma unroll
            for (int p = 0; p < 2; p++) {
                int n = wn * 32 + p * 16 + brow;
                int c = (kk + bcol) >> 3;
                int off = n * 64 + ((c ^ (n & 7)) << 3);
                uint32_t t0, t1, t2, t3;
                ldsm_x4(t0, t1, t2, t3, sptr(base + 2 * TILE + off));
                bh[2 * p][0] = t0; bh[2 * p][1] = t1;
                bh[2 * p + 1][0] = t2; bh[2 * p + 1][1] = t3;
                ldsm_x4(t0, t1, t2, t3, sptr(base + 3 * TILE + off));
                bl[2 * p][0] = t0; bl[2 * p][1] = t1;
                bl[2 * p + 1][0] = t2; bl[2 * p + 1][1] = t3;
            }
            #pragma unroll
            for (int mf = 0; mf < 4; mf++)
                #pragma unroll
                for (int nf = 0; nf < 4; nf++)
                    mma_bf16(acc[mf][nf], ah[mf], bh[nf]);
            #pragma unroll
            for (int mf = 0; mf < 4; mf++)
                #pragma unroll
                for (int nf = 0; nf < 4; nf++)
                    mma_bf16(acc[mf][nf], ah[mf], bl[nf]);
            #pragma unroll
            for (int mf = 0; mf < 4; mf++)
                #pragma unroll
                for (int nf = 0; nf < 4; nf++)
                    mma_bf16(acc[mf][nf], al[mf], bh[nf]);
        }
    };

    const int nk = K >> 6;
    load_stage(0, 0);
    cp_commit();
    for (int ch = 0; ch < nk; ch++) {
        if (ch + 1 < nk) {
            load_stage((ch + 1) & 1, (ch + 1) << 6);
            cp_commit();
            cp_wait<1>();
        } else {
            cp_wait<0>();
        }
        __syncthreads();
        compute_stage(ch & 1);
        __syncthreads();
    }

    // epilogue
    const int r0  = lane >> 2;
    const int cc0 = (lane & 3) * 2;
    #pragma unroll
    for (int mf = 0; mf < 4; mf++) {
        #pragma unroll
        for (int nf = 0; nf < 4; nf++) {
            int row = bm + wm * 64 + mf * 16 + r0;
            int col = bn + wn * 32 + nf * 8 + cc0;
            float2 v0 = make_float2(acc[mf][nf][0], acc[mf][nf][1]);
            float2 v1 = make_float2(acc[mf][nf][2], acc[mf][nf][3]);
            if (EPI) {
                float b0 = bias[col], b1 = bias[col + 1];
                v0.x += b0; v0.y += b1; v1.x += b0; v1.y += b1;
                if (EPI == 1) {
                    v0.x = v0.x > 0.f ? v0.x : 0.01f * v0.x;
                    v0.y = v0.y > 0.f ? v0.y : 0.01f * v0.y;
                    v1.x = v1.x > 0.f ? v1.x : 0.01f * v1.x;
                    v1.y = v1.y > 0.f ? v1.y : 0.01f * v1.y;
                }
            }
            if (OUT == 0) {
                *(float2*)(C + (size_t)row * N + col)       = v0;
                *(float2*)(C + (size_t)(row + 8) * N + col) = v1;
            } else {
                bf16 h0, h1, l0, l1;
                split1(v0.x, h0, l0); split1(v0.y, h1, l1);
                *(bf162*)(Ch + (size_t)row * N + col) = __halves2bfloat162(h0, h1);
                *(bf162*)(Cl + (size_t)row * N + col) = __halves2bfloat162(l0, l1);
                split1(v1.x, h0, l0); split1(v1.y, h1, l1);
                *(bf162*)(Ch + (size_t)(row + 8) * N + col) = __halves2bfloat162(h0, h1);
                *(bf162*)(Cl + (size_t)(row + 8) * N + col) = __halves2bfloat162(l0, l1);
            }
        }
    }
}

// ---------------------------------------------------------------------------
// Fused attention (flash-style), fp32 math; writes split bf16 hi/lo output.
// ---------------------------------------------------------------------------
__global__ __launch_bounds__(256)
void attn_kernel(const float* __restrict__ Q, const float* __restrict__ Kg,
                 const float* __restrict__ Vg, const int* __restrict__ vlen,
                 int per_query, bf16* __restrict__ Oh, bf16* __restrict__ Ol)
{
    __shared__ float Qs[64 * 64];
    __shared__ float KPs[64 * 64];
    __shared__ float Vs[64 * 64];

    const int b  = blockIdx.z;
    const int h  = blockIdx.y;
    const int q0 = blockIdx.x * 64;
    const int tid = threadIdx.x;
    const int q  = tid >> 2;
    const int qu = tid & 3;
    const size_t rowbase = ((size_t)b * TT) * DD + h * DH;

    #pragma unroll
    for (int u = 0; u < 4; u++) {
        int l = tid + u * 256;
        int r = l >> 4, c4 = (l & 15) * 4;
        *(float4*)&Qs[r * 64 + c4] =
            *(const float4*)(Q + rowbase + (size_t)(q0 + r) * DD + c4);
    }

    const int vlq = per_query ? vlen[b * TT + q0 + q] : vlen[b];

    int v = vlq;
    #pragma unroll
    for (int off = 16; off; off >>= 1)
        v = max(v, __shfl_xor_sync(0xffffffffu, v, off));
    if ((tid & 31) == 0) ((int*)KPs)[tid >> 5] = v;
    __syncthreads();
    int maxvl = ((int*)KPs)[0];
    #pragma unroll
    for (int i = 1; i < 8; i++) maxvl = max(maxvl, ((int*)KPs)[i]);

    float m = -1e30f, lsum = 0.f;
    float o[16];
    #pragma unroll
    for (int i = 0; i < 16; i++) o[i] = 0.f;

    const int ktiles = (maxvl + 63) >> 6;

    for (int kt = 0; kt < ktiles; kt++) {
        const int k0g = kt * 64;
        __syncthreads();
        #pragma unroll
        for (int u = 0; u < 4; u++) {
            int l = tid + u * 256;
            int r = l >> 4, c4 = (l & 15) * 4;
            *(float4*)&KPs[r * 64 + c4] =
                *(const float4*)(Kg + rowbase + (size_t)(k0g + r) * DD + c4);
            *(float4*)&Vs[r * 64 + c4] =
                *(const float4*)(Vg + rowbase + (size_t)(k0g + r) * DD + c4);
        }
        __syncthreads();

        float s[16];
        #pragma unroll
        for (int j = 0; j < 16; j++) s[j] = 0.f;
        #pragma unroll
        for (int d4 = 0; d4 < 16; d4++) {
            float4 qv = *(const float4*)&Qs[q * 64 + d4 * 4];
            #pragma unroll
            for (int j = 0; j < 16; j++) {
                float4 kv = *(const float4*)&KPs[(qu * 16 + j) * 64 + d4 * 4];
                s[j] += qv.x * kv.x + qv.y * kv.y + qv.z * kv.z + qv.w * kv.w;
            }
        }
        __syncthreads();

        float tmax = -1e30f;
        #pragma unroll
        for (int j = 0; j < 16; j++) {
            s[j] *= 0.125f;
            if (k0g + qu * 16 + j >= vlq) s[j] = -1e10f;
            tmax = fmaxf(tmax, s[j]);
        }
        tmax = fmaxf(tmax, __shfl_xor_sync(0xffffffffu, tmax, 1));
        tmax = fmaxf(tmax, __shfl_xor_sync(0xffffffffu, tmax, 2));
        const float mn = fmaxf(m, tmax);
        const float alpha = expf(m - mn);

        float psum = 0.f;
        #pragma unroll
        for (int j = 0; j < 16; j++) {
            float p = expf(s[j] - mn);
            KPs[q * 64 + qu * 16 + j] = p;
            psum += p;
        }
        psum += __shfl_xor_sync(0xffffffffu, psum, 1);
        psum += __shfl_xor_sync(0xffffffffu, psum, 2);
        lsum = lsum * alpha + psum;
        m = mn;
        #pragma unroll
        for (int i = 0; i < 16; i++) o[i] *= alpha;
        __syncthreads();

        #pragma unroll
        for (int k = 0; k < 64; k++) {
            float p = KPs[q * 64 + k];
            #pragma unroll
            for (int i4 = 0; i4 < 4; i4++) {
                float4 vv = *(const float4*)&Vs[k * 64 + qu * 16 + i4 * 4];
                o[i4 * 4 + 0] = fmaf(p, vv.x, o[i4 * 4 + 0]);
                o[i4 * 4 + 1] = fmaf(p, vv.y, o[i4 * 4 + 1]);
                o[i4 * 4 + 2] = fmaf(p, vv.z, o[i4 * 4 + 2]);
                o[i4 * 4 + 3] = fmaf(p, vv.w, o[i4 * 4 + 3]);
            }
        }
    }

    const float inv = 1.f / lsum;
    const size_t base = rowbase + (size_t)(q0 + q) * DD + qu * 16;
    #pragma unroll
    for (int i2 = 0; i2 < 8; i2++) {
        float a = o[i2 * 2] * inv, c = o[i2 * 2 + 1] * inv;
        bf16 h0, l0, h1, l1;
        split1(a, h0, l0); split1(c, h1, l1);
        *(bf162*)(Oh + base + i2 * 2) = __halves2bfloat162(h0, h1);
        *(bf162*)(Ol + base + i2 * 2) = __halves2bfloat162(l0, l1);
    }
}

// ---------------------------------------------------------------------------
// out[row] = LayerNorm(x[row] + y[row]) * gamma + beta, D=512.
// SPLIT=1: also write bf16 hi/lo of the result.
// ---------------------------------------------------------------------------
template<int SPLIT>
__global__ __launch_bounds__(128)
void add_ln_kernel(const float* __restrict__ x, const float* __restrict__ y,
                   const float* __restrict__ g, const float* __restrict__ be,
                   float* __restrict__ out, bf16* __restrict__ oh,
                   bf16* __restrict__ ol)
{
    __shared__ float ws[4], ws2[4];
    const int row = blockIdx.x;
    const int tid = threadIdx.x;

    float4 xv = ((const float4*)(x + (size_t)row * DD))[tid];
    float4 yv = ((const float4*)(y + (size_t)row * DD))[tid];
    float4 v;
    v.x = xv.x + yv.x; v.y = xv.y + yv.y; v.z = xv.z + yv.z; v.w = xv.w + yv.w;

    float s  = v.x + v.y + v.z + v.w;
    float s2 = v.x * v.x + v.y * v.y + v.z * v.z + v.w * v.w;
    #pragma unroll
    for (int off = 16; off; off >>= 1) {
        s  += __shfl_xor_sync(0xffffffffu, s,  off);
        s2 += __shfl_xor_sync(0xffffffffu, s2, off);
    }
    if ((tid & 31) == 0) { ws[tid >> 5] = s; ws2[tid >> 5] = s2; }
    __syncthreads();
    s  = ws[0]  + ws[1]  + ws[2]  + ws[3];
    s2 = ws2[0] + ws2[1] + ws2[2] + ws2[3];

    const float mean = s * (1.f / DD);
    const float var  = s2 * (1.f / DD) - mean * mean;
    const float r    = rsqrtf(var + 1e-5f);

    float4 gv = ((const float4*)g)[tid];
    float4 bv = ((const float4*)be)[tid];
    float4 w;
    w.x = (v.x - mean) * r * gv.x + bv.x;
    w.y = (v.y - mean) * r * gv.y + bv.y;
    w.z = (v.z - mean) * r * gv.z + bv.z;
    w.w = (v.w - mean) * r * gv.w + bv.w;
    ((float4*)(out + (size_t)row * DD))[tid] = w;

    if (SPLIT) {
        bf16 h0, h1, h2, h3, l0, l1, l2, l3;
        split1(w.x, h0, l0); split1(w.y, h1, l1);
        split1(w.z, h2, l2); split1(w.w, h3, l3);
        size_t o4 = (size_t)row * DD + tid * 4;
        *(bf162*)(oh + o4)     = __halves2bfloat162(h0, h1);
        *(bf162*)(oh + o4 + 2) = __halves2bfloat162(h2, h3);
        *(bf162*)(ol + o4)     = __halves2bfloat162(l0, l1);
        *(bf162*)(ol + o4 + 2) = __halves2bfloat162(l2, l3);
    }
}

// ---------------------------------------------------------------------------
// Host driver
// ---------------------------------------------------------------------------
template<typename T>
static T* symaddr(const void* sym)
{
    void* p = nullptr;
    cudaGetSymbolAddress(&p, sym);
    return (T*)p;
}

extern "C" void kernel_launch(void* const* d_in, const int* in_sizes, int n_in,
                              void* d_out, int out_size)
{
    (void)in_sizes; (void)n_in; (void)out_size;

    const float* X    = (const float*)d_in[0];
    const float* enc  = (const float*)d_in[1];
    const int*   dvl  = (const int*)d_in[2];
    const int*   evl  = (const int*)d_in[3];
    const float* Wmat[8];
    for (int i = 0; i < 8; i++) Wmat[i] = (const float*)d_in[4 + i];
    const float* W1   = (const float*)d_in[12];
    const float* b1   = (const float*)d_in[13];
    const float* W2   = (const float*)d_in[14];
    const float* b2   = (const float*)d_in[15];
    const float* g1   = (const float*)d_in[16];
    const float* be1  = (const float*)d_in[17];
    const float* g2   = (const float*)d_in[18];
    const float* be2  = (const float*)d_in[19];
    const float* g3   = (const float*)d_in[20];
    const float* be3  = (const float*)d_in[21];
    float* out = (float*)d_out;

    float* Qb = symaddr<float>(g_Q);
    float* Kb = symaddr<float>(g_K);
    float* Vb = symaddr<float>(g_V);
    float* Tb = symaddr<float>(g_T);
    float* Yb = symaddr<float>(g_Y);
    float* Zb = symaddr<float>(g_Z);
    bf16* Xh = symaddr<bf16>(g_Xh);   bf16* Xl = symaddr<bf16>(g_Xl);
    bf16* Eh = symaddr<bf16>(g_Eh);   bf16* El = symaddr<bf16>(g_El);
    bf16* Yh = symaddr<bf16>(g_Yh);   bf16* Yl = symaddr<bf16>(g_Yl);
    bf16* Zh = symaddr<bf16>(g_Zh);   bf16* Zl = symaddr<bf16>(g_Zl);
    bf16* AOh = symaddr<bf16>(g_AOh); bf16* AOl = symaddr<bf16>(g_AOl);
    bf16* Hh = symaddr<bf16>(g_Hh);   bf16* Hl = symaddr<bf16>(g_Hl);
    bf16* Wh = symaddr<bf16>(g_Wh);   bf16* Wl = symaddr<bf16>(g_Wl);
    bf16* W1h = symaddr<bf16>(g_W1h); bf16* W1l = symaddr<bf16>(g_W1l);
    bf16* W2h = symaddr<bf16>(g_W2h); bf16* W2l = symaddr<bf16>(g_W2l);

    const int SMEM = 2 * 4 * 128 * 64 * (int)sizeof(bf16);   // 128KB
    cudaFuncSetAttribute(bgemm2<0, 0>, cudaFuncAttributeMaxDynamicSharedMemorySize, SMEM);
    cudaFuncSetAttribute(bgemm2<1, 1>, cudaFuncAttributeMaxDynamicSharedMemorySize, SMEM);
    cudaFuncSetAttribute(bgemm2<2, 0>, cudaFuncAttributeMaxDynamicSharedMemorySize, SMEM);

    const int M = NTOK;
    dim3 gD(DD / 128, M / 128);     // N=512 GEMMs
    dim3 gF(FFN / 128, M / 128);    // N=2048 GEMM
    dim3 gA(TT / 64, HH, BB);       // attention

    // ---- splits (inputs + weights) ----
    split_kernel<<<(NTOK * DD / 4 + 255) / 256, 256>>>(X,   Xh, Xl, NTOK * DD / 4);
    split_kernel<<<(NTOK * DD / 4 + 255) / 256, 256>>>(enc, Eh, El, NTOK * DD / 4);
    for (int i = 0; i < 8; i++)
        split_kernel<<<(DD * DD / 4 + 255) / 256, 256>>>(Wmat[i],
            Wh + (size_t)i * DD * DD, Wl + (size_t)i * DD * DD, DD * DD / 4);
    split_kernel<<<(FFN * DD / 4 + 255) / 256, 256>>>(W1, W1h, W1l, FFN * DD / 4);
    split_kernel<<<(DD * FFN / 4 + 255) / 256, 256>>>(W2, W2h, W2l, DD * FFN / 4);

    const size_t WD = (size_t)DD * DD;

    // ---- self-attention ----
    bgemm2<0, 0><<<gD, 256, SMEM>>>(Xh, Xl, Wh + 0 * WD, Wl + 0 * WD, nullptr, Qb, nullptr, nullptr, M, DD, DD);
    bgemm2<0, 0><<<gD, 256, SMEM>>>(Xh, Xl, Wh + 1 * WD, Wl + 1 * WD, nullptr, Kb, nullptr, nullptr, M, DD, DD);
    bgemm2<0, 0><<<gD, 256, SMEM>>>(Xh, Xl, Wh + 2 * WD, Wl + 2 * WD, nullptr, Vb, nullptr, nullptr, M, DD, DD);
    attn_kernel<<<gA, 256>>>(Qb, Kb, Vb, dvl, 1, AOh, AOl);
    bgemm2<0, 0><<<gD, 256, SMEM>>>(AOh, AOl, Wh + 3 * WD, Wl + 3 * WD, nullptr, Tb, nullptr, nullptr, M, DD, DD);
    add_ln_kernel<1><<<M, 128>>>(X, Tb, g1, be1, Yb, Yh, Yl);

    // ---- cross-attention ----
    bgemm2<0, 0><<<gD, 256, SMEM>>>(Yh, Yl, Wh + 4 * WD, Wl + 4 * WD, nullptr, Qb, nullptr, nullptr, M, DD, DD);
    bgemm2<0, 0><<<gD, 256, SMEM>>>(Eh, El, Wh + 5 * WD, Wl + 5 * WD, nullptr, Kb, nullptr, nullptr, M, DD, DD);
    bgemm2<0, 0><<<gD, 256, SMEM>>>(Eh, El, Wh + 6 * WD, Wl + 6 * WD, nullptr, Vb, nullptr, nullptr, M, DD, DD);
    attn_kernel<<<gA, 256>>>(Qb, Kb, Vb, evl, 0, AOh, AOl);
    bgemm2<0, 0><<<gD, 256, SMEM>>>(AOh, AOl, Wh + 7 * WD, Wl + 7 * WD, nullptr, Tb, nullptr, nullptr, M, DD, DD);
    add_ln_kernel<1><<<M, 128>>>(Yb, Tb, g2, be2, Zb, Zh, Zl);

    // ---- FFN ----
    bgemm2<1, 1><<<gF, 256, SMEM>>>(Zh, Zl, W1h, W1l, b1, nullptr, Hh, Hl, M, FFN, DD);
    bgemm2<2, 0><<<gD, 256, SMEM>>>(Hh, Hl, W2h, W2l, b2, Tb, nullptr, nullptr, M, DD, FFN);
    add_ln_kernel<0><<<M, 128>>>(Zb, Tb, g3, be3, out, nullptr, nullptr);
}

// round 8
// speedup vs baseline: 5.0340x; 3.5880x over previous
#include <cuda_runtime.h>
#include <cuda_bf16.h>
#include <math.h>
#include <stdint.h>

// Problem dims (fixed by the reference)
#define BB   32
#define TT   512
#define DD   512
#define HH   8
#define DH   64
#define FFN  2048
#define NTOK (BB*TT)   // 16384

typedef __nv_bfloat16 bf16;
typedef __nv_bfloat162 bf162;

// ---------------------------------------------------------------------------
// Scratch (device globals; no allocations allowed)
// ---------------------------------------------------------------------------
__device__ float g_T [NTOK*DD];
__device__ float g_Y [NTOK*DD];
__device__ float g_Z [NTOK*DD];
__device__ bf16 g_Xh [NTOK*DD];
__device__ bf16 g_Xl [NTOK*DD];
__device__ bf16 g_Eh [NTOK*DD];
__device__ bf16 g_El [NTOK*DD];
__device__ bf16 g_Yh [NTOK*DD];
__device__ bf16 g_Yl [NTOK*DD];
__device__ bf16 g_Zh [NTOK*DD];
__device__ bf16 g_Zl [NTOK*DD];
__device__ bf16 g_AOh[NTOK*DD];
__device__ bf16 g_AOl[NTOK*DD];
__device__ bf16 g_Qh [NTOK*DD];
__device__ bf16 g_Ql [NTOK*DD];
__device__ bf16 g_Kh [NTOK*DD];
__device__ bf16 g_Kl [NTOK*DD];
__device__ bf16 g_Vh [NTOK*DD];
__device__ bf16 g_Vl [NTOK*DD];
__device__ bf16 g_Hh [NTOK*FFN];
__device__ bf16 g_Hl [NTOK*FFN];
__device__ bf16 g_Wh [8*DD*DD];
__device__ bf16 g_Wl [8*DD*DD];
__device__ bf16 g_W1h[FFN*DD];
__device__ bf16 g_W1l[FFN*DD];
__device__ bf16 g_W2h[DD*FFN];
__device__ bf16 g_W2l[DD*FFN];

// ---------------------------------------------------------------------------
// PTX helpers
// ---------------------------------------------------------------------------
__device__ __forceinline__ uint32_t sptr(const void* p)
{
    return (uint32_t)__cvta_generic_to_shared(p);
}

__device__ __forceinline__ void ldsm_x4(uint32_t& r0, uint32_t& r1,
                                        uint32_t& r2, uint32_t& r3, uint32_t addr)
{
    asm volatile("ldmatrix.sync.aligned.m8n8.x4.shared.b16 {%0,%1,%2,%3}, [%4];"
                 : "=r"(r0), "=r"(r1), "=r"(r2), "=r"(r3) : "r"(addr));
}

__device__ __forceinline__ void ldsm_x4_t(uint32_t& r0, uint32_t& r1,
                                          uint32_t& r2, uint32_t& r3, uint32_t addr)
{
    asm volatile("ldmatrix.sync.aligned.m8n8.x4.trans.shared.b16 {%0,%1,%2,%3}, [%4];"
                 : "=r"(r0), "=r"(r1), "=r"(r2), "=r"(r3) : "r"(addr));
}

__device__ __forceinline__ void mma_bf16(float* c, const uint32_t* a, const uint32_t* b)
{
    asm volatile("mma.sync.aligned.m16n8k16.row.col.f32.bf16.bf16.f32 "
                 "{%0,%1,%2,%3}, {%4,%5,%6,%7}, {%8,%9}, {%0,%1,%2,%3};"
                 : "+f"(c[0]), "+f"(c[1]), "+f"(c[2]), "+f"(c[3])
                 : "r"(a[0]), "r"(a[1]), "r"(a[2]), "r"(a[3]),
                   "r"(b[0]), "r"(b[1]));
}

__device__ __forceinline__ void cp_async16(uint32_t saddr, const void* gaddr)
{
    asm volatile("cp.async.cg.shared.global [%0], [%1], 16;" :: "r"(saddr), "l"(gaddr));
}
__device__ __forceinline__ void cp_commit()
{
    asm volatile("cp.async.commit_group;");
}
template<int N>
__device__ __forceinline__ void cp_wait()
{
    asm volatile("cp.async.wait_group %0;" :: "n"(N));
}

__device__ __forceinline__ void split1(float v, bf16& h, bf16& l)
{
    h = __float2bfloat16(v);
    l = __float2bfloat16(v - __bfloat162float(h));
}

__device__ __forceinline__ uint32_t pack_split_hi(float a, float b)
{
    bf16 ha = __float2bfloat16(a), hb = __float2bfloat16(b);
    bf162 p = __halves2bfloat162(ha, hb);
    return *(uint32_t*)&p;
}
__device__ __forceinline__ uint32_t pack_split_lo(float a, float b)
{
    bf16 ha = __float2bfloat16(a), hb = __float2bfloat16(b);
    bf16 la = __float2bfloat16(a - __bfloat162float(ha));
    bf16 lb = __float2bfloat16(b - __bfloat162float(hb));
    bf162 p = __halves2bfloat162(la, lb);
    return *(uint32_t*)&p;
}

// e^x for x <= 0, FMA-pipe polynomial (no MUFU). ~3e-8 rel err.
__device__ __forceinline__ float fexp(float x)
{
    float t = fmaxf(x * 1.44269504089f, -126.0f);
    float fn = t + 12582912.0f;            // 1.5*2^23: round-to-nearest int
    float n  = fn - 12582912.0f;
    float f  = t - n;
    float p = 1.54035304e-4f;
    p = fmaf(p, f, 1.33335581e-3f);
    p = fmaf(p, f, 9.61812910e-3f);
    p = fmaf(p, f, 5.55041087e-2f);
    p = fmaf(p, f, 2.40226507e-1f);
    p = fmaf(p, f, 6.93147182e-1f);
    p = fmaf(p, f, 1.0f);
    return p * __int_as_float(((int)n + 127) << 23);
}

// ---------------------------------------------------------------------------
// split_kernel: fp32 x -> bf16 hi/lo, float4-vectorized
// ---------------------------------------------------------------------------
__global__ __launch_bounds__(256)
void split_kernel(const float* __restrict__ x, bf16* __restrict__ h,
                  bf16* __restrict__ l, int n4)
{
    int i = blockIdx.x * 256 + threadIdx.x;
    if (i >= n4) return;
    float4 v = ((const float4*)x)[i];
    bf16 hx, hy, hz, hw, lx, ly, lz, lw;
    split1(v.x, hx, lx); split1(v.y, hy, ly);
    split1(v.z, hz, lz); split1(v.w, hw, lw);
    ((bf162*)h)[i * 2]     = __halves2bfloat162(hx, hy);
    ((bf162*)h)[i * 2 + 1] = __halves2bfloat162(hz, hw);
    ((bf162*)l)[i * 2]     = __halves2bfloat162(lx, ly);
    ((bf162*)l)[i * 2 + 1] = __halves2bfloat162(lz, lw);
}

// ---------------------------------------------------------------------------
// bf16x3 split tensor-core GEMM (mma.sync), pre-split operands.
//   C[M,N] = A[M,K]*B[N,K]^T ~ fp32  via AhBh + AhBl + AlBh.
// BM=BN=128, BK=64, 512 threads (16 warps 4x4), warp tile 32x32.
// 2-stage cp.async; 128B swizzled rows. EPI: 0 none, 1 +bias+LReLU, 2 +bias.
// OUT: 0 fp32 C, 1 split bf16 Ch/Cl.
// ---------------------------------------------------------------------------
template<int EPI, int OUT>
__global__ __launch_bounds__(512)
void bgemm3(const bf16* __restrict__ Ahg, const bf16* __restrict__ Alg,
            const bf16* __restrict__ Bhg, const bf16* __restrict__ Blg,
            const float* __restrict__ bias,
            float* __restrict__ C, bf16* __restrict__ Ch, bf16* __restrict__ Cl,
            int M, int N, int K)
{
    extern __shared__ __align__(16) uint8_t smp[];
    constexpr uint32_t TILEB  = 128 * 64 * 2;   // 16KB per tile
    constexpr uint32_t STAGEB = 4 * TILEB;      // Ah, Al, Bh, Bl

    const int bm   = blockIdx.y * 128;
    const int bn   = blockIdx.x * 128;
    const int tid  = threadIdx.x;
    const int lane = tid & 31;
    const int wid  = tid >> 5;
    const int wm   = wid >> 2;   // 0..3
    const int wn   = wid & 3;    // 0..3
    const uint32_t smbase = sptr(smp);

    float acc[2][4][4];
    #pragma unroll
    for (int i = 0; i < 2; i++)
        #pragma unroll
        for (int j = 0; j < 4; j++)
            #pragma unroll
            for (int t = 0; t < 4; t++) acc[i][j][t] = 0.f;

    const int arow = ((lane >> 3) & 1) * 8 + (lane & 7);
    const int acol = ((lane >> 4) & 1) * 8;
    const int brow = ((lane >> 4) & 1) * 8 + (lane & 7);
    const int bcol = ((lane >> 3) & 1) * 8;

    auto load_stage = [&](int s, int k0) {
        const uint32_t base = smbase + (uint32_t)s * STAGEB;
        #pragma unroll
        for (int t = 0; t < 2; t++) {
            int idx = tid + t * 512;          // 0..1023 chunks per tile
            int row = idx >> 3, c = idx & 7;
            uint32_t boff = (uint32_t)row * 128 + ((uint32_t)(c ^ (row & 7)) << 4);
            const size_t ga = (size_t)(bm + row) * K + k0 + c * 8;
            const size_t gb = (size_t)(bn + row) * K + k0 + c * 8;
            cp_async16(base + boff,             Ahg + ga);
            cp_async16(base + TILEB + boff,     Alg + ga);
            cp_async16(base + 2 * TILEB + boff, Bhg + gb);
            cp_async16(base + 3 * TILEB + boff, Blg + gb);
        }
    };

    auto compute_stage = [&](int s) {
        const uint32_t base = smbase + (uint32_t)s * STAGEB;
        #pragma unroll
        for (int kk = 0; kk < 64; kk += 16) {
            uint32_t ah[2][4], al[2][4], bh[4][2], bl[4][2];
            #pragma unroll
            for (int mf = 0; mf < 2; mf++) {
                int r = wm * 32 + mf * 16 + arow;
                int c = (kk + acol) >> 3;
                uint32_t off = (uint32_t)r * 128 + ((uint32_t)(c ^ (r & 7)) << 4);
                ldsm_x4(ah[mf][0], ah[mf][1], ah[mf][2], ah[mf][3], base + off);
                ldsm_x4(al[mf][0], al[mf][1], al[mf][2], al[mf][3], base + TILEB + off);
            }
            #pragma unroll
            for (int p = 0; p < 2; p++) {
                int n = wn * 32 + p * 16 + brow;
                int c = (kk + bcol) >> 3;
                uint32_t off = (uint32_t)n * 128 + ((uint32_t)(c ^ (n & 7)) << 4);
                uint32_t t0, t1, t2, t3;
                ldsm_x4(t0, t1, t2, t3, base + 2 * TILEB + off);
                bh[2 * p][0] = t0; bh[2 * p][1] = t1;
                bh[2 * p + 1][0] = t2; bh[2 * p + 1][1] = t3;
                ldsm_x4(t0, t1, t2, t3, base + 3 * TILEB + off);
                bl[2 * p][0] = t0; bl[2 * p][1] = t1;
                bl[2 * p + 1][0] = t2; bl[2 * p + 1][1] = t3;
            }
            #pragma unroll
            for (int mf = 0; mf < 2; mf++)
                #pragma unroll
                for (int nf = 0; nf < 4; nf++) {
                    mma_bf16(acc[mf][nf], ah[mf], bh[nf]);
                    mma_bf16(acc[mf][nf], ah[mf], bl[nf]);
                    mma_bf16(acc[mf][nf], al[mf], bh[nf]);
                }
        }
    };

    const int nk = K >> 6;
    load_stage(0, 0);
    cp_commit();
    for (int ch = 0; ch < nk; ch++) {
        if (ch + 1 < nk) {
            load_stage((ch + 1) & 1, (ch + 1) << 6);
            cp_commit();
            cp_wait<1>();
        } else {
            cp_wait<0>();
        }
        __syncthreads();
        compute_stage(ch & 1);
        __syncthreads();
    }

    // epilogue
    const int r0  = lane >> 2;
    const int cc0 = (lane & 3) * 2;
    #pragma unroll
    for (int mf = 0; mf < 2; mf++) {
        #pragma unroll
        for (int nf = 0; nf < 4; nf++) {
            int row = bm + wm * 32 + mf * 16 + r0;
            int col = bn + wn * 32 + nf * 8 + cc0;
            float2 v0 = make_float2(acc[mf][nf][0], acc[mf][nf][1]);
            float2 v1 = make_float2(acc[mf][nf][2], acc[mf][nf][3]);
            if (EPI) {
                float b0 = bias[col], b1 = bias[col + 1];
                v0.x += b0; v0.y += b1; v1.x += b0; v1.y += b1;
                if (EPI == 1) {
                    v0.x = v0.x > 0.f ? v0.x : 0.01f * v0.x;
                    v0.y = v0.y > 0.f ? v0.y : 0.01f * v0.y;
                    v1.x = v1.x > 0.f ? v1.x : 0.01f * v1.x;
                    v1.y = v1.y > 0.f ? v1.y : 0.01f * v1.y;
                }
            }
            if (OUT == 0) {
                *(float2*)(C + (size_t)row * N + col)       = v0;
                *(float2*)(C + (size_t)(row + 8) * N + col) = v1;
            } else {
                *(uint32_t*)(Ch + (size_t)row * N + col)       = pack_split_hi(v0.x, v0.y);
                *(uint32_t*)(Cl + (size_t)row * N + col)       = pack_split_lo(v0.x, v0.y);
                *(uint32_t*)(Ch + (size_t)(row + 8) * N + col) = pack_split_hi(v1.x, v1.y);
                *(uint32_t*)(Cl + (size_t)(row + 8) * N + col) = pack_split_lo(v1.x, v1.y);
            }
        }
    }
}

// ---------------------------------------------------------------------------
// FA2-style attention on tensor cores (bf16x3 S and PV), poly-exp softmax.
// CTA = (b, h, 64-query tile), 128 threads (4 warps x 16 q-rows).
// Q/K/V pre-split bf16 hi/lo, [tok][512], head at cols h*64..h*64+63.
// Dynamic smem 48KB: Qh,Ql,Kh,Kl,Vh,Vl tiles (64x64 each, 128B swizzled rows).
// ---------------------------------------------------------------------------
__global__ __launch_bounds__(128)
void attn_tc(const bf16* __restrict__ Qhg, const bf16* __restrict__ Qlg,
             const bf16* __restrict__ Khg, const bf16* __restrict__ Klg,
             const bf16* __restrict__ Vhg, const bf16* __restrict__ Vlg,
             const int* __restrict__ vlen, int per_query,
             bf16* __restrict__ Oh, bf16* __restrict__ Ol)
{
    extern __shared__ __align__(16) uint8_t smp[];
    __shared__ int s_red[4];
    constexpr uint32_t OQH = 0, OQL = 8192, OKH = 16384, OKL = 24576;
    constexpr uint32_t OVH = 32768, OVL = 40960;

    const int b  = blockIdx.z;
    const int h  = blockIdx.y;
    const int q0 = blockIdx.x * 64;
    const int tid  = threadIdx.x;
    const int lane = tid & 31;
    const int w    = tid >> 5;
    const uint32_t smbase = sptr(smp);
    const size_t rowbase = ((size_t)b * TT) * DD + h * DH;

    const int arow = ((lane >> 3) & 1) * 8 + (lane & 7);
    const int acol = ((lane >> 4) & 1) * 8;
    const int brow = ((lane >> 4) & 1) * 8 + (lane & 7);
    const int bcol = ((lane >> 3) & 1) * 8;

    // tile loader: 64 rows x 64 bf16 (8 chunks of 16B per row)
    auto ldtile = [&](uint32_t dst, const bf16* src, int row0) {
        #pragma unroll
        for (int t = 0; t < 4; t++) {
            int idx = tid + t * 128;          // 0..511
            int row = idx >> 3, c = idx & 7;
            uint32_t boff = dst + (uint32_t)row * 128 + ((uint32_t)(c ^ (row & 7)) << 4);
            cp_async16(smbase + boff, src + rowbase + (size_t)(row0 + row) * DD + c * 8);
        }
    };

    // load Q tile
    ldtile(OQH, Qhg, q0);
    ldtile(OQL, Qlg, q0);
    cp_commit();

    // valid lens
    const int r0g = q0 + w * 16 + (lane >> 2);
    const int vl0 = per_query ? vlen[b * TT + r0g]     : vlen[b];
    const int vl1 = per_query ? vlen[b * TT + r0g + 8] : vlen[b];

    int v = per_query ? ((tid < 64) ? vlen[b * TT + q0 + tid] : 1) : vlen[b];
    #pragma unroll
    for (int off = 16; off; off >>= 1) v = max(v, __shfl_xor_sync(0xffffffffu, v, off));
    if (lane == 0) s_red[w] = v;

    cp_wait<0>();
    __syncthreads();
    const int maxvl = max(max(s_red[0], s_red[1]), max(s_red[2], s_red[3]));

    // Q fragments (m16 x k64): 4 k-frags, hi+lo
    uint32_t qh[4][4], ql[4][4];
    #pragma unroll
    for (int kf = 0; kf < 4; kf++) {
        int r = w * 16 + arow;
        int c = (kf * 16 + acol) >> 3;
        uint32_t off = (uint32_t)r * 128 + ((uint32_t)(c ^ (r & 7)) << 4);
        ldsm_x4(qh[kf][0], qh[kf][1], qh[kf][2], qh[kf][3], smbase + OQH + off);
        ldsm_x4(ql[kf][0], ql[kf][1], ql[kf][2], ql[kf][3], smbase + OQL + off);
    }

    float m0 = -1e30f, m1 = -1e30f, l0 = 0.f, l1 = 0.f;
    float o[8][4];
    #pragma unroll
    for (int i = 0; i < 8; i++)
        #pragma unroll
        for (int j = 0; j < 4; j++) o[i][j] = 0.f;

    const int ktiles = (maxvl + 63) >> 6;

    for (int kt = 0; kt < ktiles; kt++) {
        __syncthreads();           // previous tile consumers done
        ldtile(OKH, Khg, kt * 64);
        ldtile(OKL, Klg, kt * 64);
        ldtile(OVH, Vhg, kt * 64);
        ldtile(OVL, Vlg, kt * 64);
        cp_commit();
        cp_wait<0>();
        __syncthreads();

        // ---- S = Q K^T (bf16x3) ----
        float s[8][4];
        #pragma unroll
        for (int i = 0; i < 8; i++)
            #pragma unroll
            for (int j = 0; j < 4; j++) s[i][j] = 0.f;

        #pragma unroll
        for (int kf = 0; kf < 4; kf++) {
            uint32_t bh[8][2], bl[8][2];
            #pragma unroll
            for (int p = 0; p < 4; p++) {
                int n = p * 16 + brow;
                int c = (kf * 16 + bcol) >> 3;
                uint32_t off = (uint32_t)n * 128 + ((uint32_t)(c ^ (n & 7)) << 4);
                uint32_t t0, t1, t2, t3;
                ldsm_x4(t0, t1, t2, t3, smbase + OKH + off);
                bh[2 * p][0] = t0; bh[2 * p][1] = t1;
                bh[2 * p + 1][0] = t2; bh[2 * p + 1][1] = t3;
                ldsm_x4(t0, t1, t2, t3, smbase + OKL + off);
                bl[2 * p][0] = t0; bl[2 * p][1] = t1;
                bl[2 * p + 1][0] = t2; bl[2 * p + 1][1] = t3;
            }
            #pragma unroll
            for (int nf = 0; nf < 8; nf++) {
                mma_bf16(s[nf], qh[kf], bh[nf]);
                mma_bf16(s[nf], qh[kf], bl[nf]);
                mma_bf16(s[nf], ql[kf], bh[nf]);
            }
        }

        // ---- scale + mask ----
        const int kbase = kt * 64 + (lane & 3) * 2;
        #pragma unroll
        for (int nf = 0; nf < 8; nf++) {
            int k0c = kbase + nf * 8;
            s[nf][0] = (k0c     < vl0) ? s[nf][0] * 0.125f : -1e10f;
            s[nf][1] = (k0c + 1 < vl0) ? s[nf][1] * 0.125f : -1e10f;
            s[nf][2] = (k0c     < vl1) ? s[nf][2] * 0.125f : -1e10f;
            s[nf][3] = (k0c + 1 < vl1) ? s[nf][3] * 0.125f : -1e10f;
        }

        // ---- row max ----
        float rm0 = -1e30f, rm1 = -1e30f;
        #pragma unroll
        for (int nf = 0; nf < 8; nf++) {
            rm0 = fmaxf(rm0, fmaxf(s[nf][0], s[nf][1]));
            rm1 = fmaxf(rm1, fmaxf(s[nf][2], s[nf][3]));
        }
        rm0 = fmaxf(rm0, __shfl_xor_sync(0xffffffffu, rm0, 1));
        rm0 = fmaxf(rm0, __shfl_xor_sync(0xffffffffu, rm0, 2));
        rm1 = fmaxf(rm1, __shfl_xor_sync(0xffffffffu, rm1, 1));
        rm1 = fmaxf(rm1, __shfl_xor_sync(0xffffffffu, rm1, 2));

        const float mn0 = fmaxf(m0, rm0), mn1 = fmaxf(m1, rm1);
        const float al0 = fexp(m0 - mn0), al1 = fexp(m1 - mn1);
        m0 = mn0; m1 = mn1;

        // ---- exp + pack P (split hi/lo) ----
        float ps0 = 0.f, ps1 = 0.f;
        uint32_t phi[4][4], plo[4][4];
        #pragma unroll
        for (int nf = 0; nf < 8; nf++) {
            float p0 = fexp(s[nf][0] - mn0);
            float p1 = fexp(s[nf][1] - mn0);
            float p2 = fexp(s[nf][2] - mn1);
            float p3 = fexp(s[nf][3] - mn1);
            ps0 += p0 + p1; ps1 += p2 + p3;
            int kf = nf >> 1, half = nf & 1;
            phi[kf][2 * half]     = pack_split_hi(p0, p1);
            phi[kf][2 * half + 1] = pack_split_hi(p2, p3);
            plo[kf][2 * half]     = pack_split_lo(p0, p1);
            plo[kf][2 * half + 1] = pack_split_lo(p2, p3);
        }
        ps0 += __shfl_xor_sync(0xffffffffu, ps0, 1);
        ps0 += __shfl_xor_sync(0xffffffffu, ps0, 2);
        ps1 += __shfl_xor_sync(0xffffffffu, ps1, 1);
        ps1 += __shfl_xor_sync(0xffffffffu, ps1, 2);
        l0 = l0 * al0 + ps0;
        l1 = l1 * al1 + ps1;

        #pragma unroll
        for (int nf = 0; nf < 8; nf++) {
            o[nf][0] *= al0; o[nf][1] *= al0;
            o[nf][2] *= al1; o[nf][3] *= al1;
        }

        // ---- O += P V (bf16x3), V via ldmatrix.trans ----
        const int tq = lane >> 3, rq = lane & 7;
        #pragma unroll
        for (int df2 = 0; df2 < 4; df2++) {
            uint32_t vh[4][4], vl_[4][4];
            #pragma unroll
            for (int kf = 0; kf < 4; kf++) {
                int krow = kf * 16 + (tq & 1) * 8 + rq;
                int c = df2 * 2 + (tq >> 1);
                uint32_t off = (uint32_t)krow * 128 + ((uint32_t)(c ^ (krow & 7)) << 4);
                ldsm_x4_t(vh[kf][0], vh[kf][1], vh[kf][2], vh[kf][3], smbase + OVH + off);
                ldsm_x4_t(vl_[kf][0], vl_[kf][1], vl_[kf][2], vl_[kf][3], smbase + OVL + off);
            }
            #pragma unroll
            for (int kf = 0; kf < 4; kf++) {
                mma_bf16(o[2 * df2],     phi[kf], &vh[kf][0]);
                mma_bf16(o[2 * df2 + 1], phi[kf], &vh[kf][2]);
                mma_bf16(o[2 * df2],     phi[kf], &vl_[kf][0]);
                mma_bf16(o[2 * df2 + 1], phi[kf], &vl_[kf][2]);
                mma_bf16(o[2 * df2],     plo[kf], &vh[kf][0]);
                mma_bf16(o[2 * df2 + 1], plo[kf], &vh[kf][2]);
            }
        }
    }

    // ---- normalize + write split output ----
    const float inv0 = 1.f / l0, inv1 = 1.f / l1;
    const size_t rA = rowbase + (size_t)r0g * DD;
    const size_t rB = rowbase + (size_t)(r0g + 8) * DD;
    const int c0 = (lane & 3) * 2;
    #pragma unroll
    for (int nf = 0; nf < 8; nf++) {
        int col = nf * 8 + c0;
        float a0 = o[nf][0] * inv0, a1 = o[nf][1] * inv0;
        float b0 = o[nf][2] * inv1, b1 = o[nf][3] * inv1;
        *(uint32_t*)(Oh + rA + col) = pack_split_hi(a0, a1);
        *(uint32_t*)(Ol + rA + col) = pack_split_lo(a0, a1);
        *(uint32_t*)(Oh + rB + col) = pack_split_hi(b0, b1);
        *(uint32_t*)(Ol + rB + col) = pack_split_lo(b0, b1);
    }
}

// ---------------------------------------------------------------------------
// out[row] = LayerNorm(x[row] + y[row]) * gamma + beta, D=512.
// SPLIT=1: also write bf16 hi/lo of the result.
// ---------------------------------------------------------------------------
template<int SPLIT>
__global__ __launch_bounds__(128)
void add_ln_kernel(const float* __restrict__ x, const float* __restrict__ y,
                   const float* __restrict__ g, const float* __restrict__ be,
                   float* __restrict__ out, bf16* __restrict__ oh,
                   bf16* __restrict__ ol)
{
    __shared__ float ws[4], ws2[4];
    const int row = blockIdx.x;
    const int tid = threadIdx.x;

    float4 xv = ((const float4*)(x + (size_t)row * DD))[tid];
    float4 yv = ((const float4*)(y + (size_t)row * DD))[tid];
    float4 v;
    v.x = xv.x + yv.x; v.y = xv.y + yv.y; v.z = xv.z + yv.z; v.w = xv.w + yv.w;

    float s  = v.x + v.y + v.z + v.w;
    float s2 = v.x * v.x + v.y * v.y + v.z * v.z + v.w * v.w;
    #pragma unroll
    for (int off = 16; off; off >>= 1) {
        s  += __shfl_xor_sync(0xffffffffu, s,  off);
        s2 += __shfl_xor_sync(0xffffffffu, s2, off);
    }
    if ((tid & 31) == 0) { ws[tid >> 5] = s; ws2[tid >> 5] = s2; }
    __syncthreads();
    s  = ws[0]  + ws[1]  + ws[2]  + ws[3];
    s2 = ws2[0] + ws2[1] + ws2[2] + ws2[3];

    const float mean = s * (1.f / DD);
    const float var  = s2 * (1.f / DD) - mean * mean;
    const float r    = rsqrtf(var + 1e-5f);

    float4 gv = ((const float4*)g)[tid];
    float4 bv = ((const float4*)be)[tid];
    float4 w;
    w.x = (v.x - mean) * r * gv.x + bv.x;
    w.y = (v.y - mean) * r * gv.y + bv.y;
    w.z = (v.z - mean) * r * gv.z + bv.z;
    w.w = (v.w - mean) * r * gv.w + bv.w;
    ((float4*)(out + (size_t)row * DD))[tid] = w;

    if (SPLIT) {
        size_t o4 = (size_t)row * DD + tid * 4;
        *(uint32_t*)(oh + o4)     = pack_split_hi(w.x, w.y);
        *(uint32_t*)(oh + o4 + 2) = pack_split_hi(w.z, w.w);
        *(uint32_t*)(ol + o4)     = pack_split_lo(w.x, w.y);
        *(uint32_t*)(ol + o4 + 2) = pack_split_lo(w.z, w.w);
    }
}

// ---------------------------------------------------------------------------
// Host driver
// ---------------------------------------------------------------------------
template<typename T>
static T* symaddr(const void* sym)
{
    void* p = nullptr;
    cudaGetSymbolAddress(&p, sym);
    return (T*)p;
}

extern "C" void kernel_launch(void* const* d_in, const int* in_sizes, int n_in,
                              void* d_out, int out_size)
{
    (void)in_sizes; (void)n_in; (void)out_size;

    const float* X    = (const float*)d_in[0];
    const float* enc  = (const float*)d_in[1];
    const int*   dvl  = (const int*)d_in[2];
    const int*   evl  = (const int*)d_in[3];
    const float* Wmat[8];
    for (int i = 0; i < 8; i++) Wmat[i] = (const float*)d_in[4 + i];
    const float* W1   = (const float*)d_in[12];
    const float* b1   = (const float*)d_in[13];
    const float* W2   = (const float*)d_in[14];
    const float* b2   = (const float*)d_in[15];
    const float* g1   = (const float*)d_in[16];
    const float* be1  = (const float*)d_in[17];
    const float* g2   = (const float*)d_in[18];
    const float* be2  = (const float*)d_in[19];
    const float* g3   = (const float*)d_in[20];
    const float* be3  = (const float*)d_in[21];
    float* out = (float*)d_out;

    float* Tb = symaddr<float>(g_T);
    float* Yb = symaddr<float>(g_Y);
    float* Zb = symaddr<float>(g_Z);
    bf16* Xh = symaddr<bf16>(g_Xh);   bf16* Xl = symaddr<bf16>(g_Xl);
    bf16* Eh = symaddr<bf16>(g_Eh);   bf16* El = symaddr<bf16>(g_El);
    bf16* Yh = symaddr<bf16>(g_Yh);   bf16* Yl = symaddr<bf16>(g_Yl);
    bf16* Zh = symaddr<bf16>(g_Zh);   bf16* Zl = symaddr<bf16>(g_Zl);
    bf16* AOh = symaddr<bf16>(g_AOh); bf16* AOl = symaddr<bf16>(g_AOl);
    bf16* Qh = symaddr<bf16>(g_Qh);   bf16* Ql = symaddr<bf16>(g_Ql);
    bf16* Kh = symaddr<bf16>(g_Kh);   bf16* Kl = symaddr<bf16>(g_Kl);
    bf16* Vh = symaddr<bf16>(g_Vh);   bf16* Vl = symaddr<bf16>(g_Vl);
    bf16* Hh = symaddr<bf16>(g_Hh);   bf16* Hl = symaddr<bf16>(g_Hl);
    bf16* Wh = symaddr<bf16>(g_Wh);   bf16* Wl = symaddr<bf16>(g_Wl);
    bf16* W1h = symaddr<bf16>(g_W1h); bf16* W1l = symaddr<bf16>(g_W1l);
    bf16* W2h = symaddr<bf16>(g_W2h); bf16* W2l = symaddr<bf16>(g_W2l);

    const int GSMEM = 2 * 4 * 128 * 64 * 2;   // 128KB
    const int ASMEM = 6 * 64 * 64 * 2;        // 48KB
    cudaFuncSetAttribute(bgemm3<0, 0>, cudaFuncAttributeMaxDynamicSharedMemorySize, GSMEM);
    cudaFuncSetAttribute(bgemm3<0, 1>, cudaFuncAttributeMaxDynamicSharedMemorySize, GSMEM);
    cudaFuncSetAttribute(bgemm3<1, 1>, cudaFuncAttributeMaxDynamicSharedMemorySize, GSMEM);
    cudaFuncSetAttribute(bgemm3<2, 0>, cudaFuncAttributeMaxDynamicSharedMemorySize, GSMEM);
    cudaFuncSetAttribute(attn_tc, cudaFuncAttributeMaxDynamicSharedMemorySize, ASMEM);

    const int M = NTOK;
    dim3 gD(DD / 128, M / 128);     // N=512 GEMMs
    dim3 gF(FFN / 128, M / 128);    // N=2048 GEMM
    dim3 gA(TT / 64, HH, BB);       // attention

    // ---- splits (inputs + weights) ----
    split_kernel<<<(NTOK * DD / 4 + 255) / 256, 256>>>(X,   Xh, Xl, NTOK * DD / 4);
    split_kernel<<<(NTOK * DD / 4 + 255) / 256, 256>>>(enc, Eh, El, NTOK * DD / 4);
    for (int i = 0; i < 8; i++)
        split_kernel<<<(DD * DD / 4 + 255) / 256, 256>>>(Wmat[i],
            Wh + (size_t)i * DD * DD, Wl + (size_t)i * DD * DD, DD * DD / 4);
    split_kernel<<<(FFN * DD / 4 + 255) / 256, 256>>>(W1, W1h, W1l, FFN * DD / 4);
    split_kernel<<<(DD * FFN / 4 + 255) / 256, 256>>>(W2, W2h, W2l, DD * FFN / 4);

    const size_t WD = (size_t)DD * DD;

    // ---- self-attention ----
    bgemm3<0, 1><<<gD, 512, GSMEM>>>(Xh, Xl, Wh + 0 * WD, Wl + 0 * WD, nullptr, nullptr, Qh, Ql, M, DD, DD);
    bgemm3<0, 1><<<gD, 512, GSMEM>>>(Xh, Xl, Wh + 1 * WD, Wl + 1 * WD, nullptr, nullptr, Kh, Kl, M, DD, DD);
    bgemm3<0, 1><<<gD, 512, GSMEM>>>(Xh, Xl, Wh + 2 * WD, Wl + 2 * WD, nullptr, nullptr, Vh, Vl, M, DD, DD);
    attn_tc<<<gA, 128, ASMEM>>>(Qh, Ql, Kh, Kl, Vh, Vl, dvl, 1, AOh, AOl);
    bgemm3<0, 0><<<gD, 512, GSMEM>>>(AOh, AOl, Wh + 3 * WD, Wl + 3 * WD, nullptr, Tb, nullptr, nullptr, M, DD, DD);
    add_ln_kernel<1><<<M, 128>>>(X, Tb, g1, be1, Yb, Yh, Yl);

    // ---- cross-attention ----
    bgemm3<0, 1><<<gD, 512, GSMEM>>>(Yh, Yl, Wh + 4 * WD, Wl + 4 * WD, nullptr, nullptr, Qh, Ql, M, DD, DD);
    bgemm3<0, 1><<<gD, 512, GSMEM>>>(Eh, El, Wh + 5 * WD, Wl + 5 * WD, nullptr, nullptr, Kh, Kl, M, DD, DD);
    bgemm3<0, 1><<<gD, 512, GSMEM>>>(Eh, El, Wh + 6 * WD, Wl + 6 * WD, nullptr, nullptr, Vh, Vl, M, DD, DD);
    attn_tc<<<gA, 128, ASMEM>>>(Qh, Ql, Kh, Kl, Vh, Vl, evl, 0, AOh, AOl);
    bgemm3<0, 0><<<gD, 512, GSMEM>>>(AOh, AOl, Wh + 7 * WD, Wl + 7 * WD, nullptr, Tb, nullptr, nullptr, M, DD, DD);
    add_ln_kernel<1><<<M, 128>>>(Yb, Tb, g2, be2, Zb, Zh, Zl);

    // ---- FFN ----
    bgemm3<1, 1><<<gF, 512, GSMEM>>>(Zh, Zl, W1h, W1l, b1, nullptr, Hh, Hl, M, FFN, DD);
    bgemm3<2, 0><<<gD, 512, GSMEM>>>(Hh, Hl, W2h, W2l, b2, Tb, nullptr, nullptr, M, DD, FFN);
    add_ln_kernel<0><<<M, 128>>>(Zb, Tb, g3, be3, out, nullptr, nullptr);
}

// round 11
// speedup vs baseline: 5.6200x; 1.1164x over previous
#include <cuda_runtime.h>
#include <cuda_fp16.h>
#include <math.h>
#include <stdint.h>

// Problem dims (fixed by the reference)
#define BB   32
#define TT   512
#define DD   512
#define HH   8
#define DH   64
#define FFN  2048
#define NTOK (BB*TT)   // 16384

typedef __half  hf;
typedef __half2 hf2;

// ---------------------------------------------------------------------------
// Scratch (device globals; no allocations allowed)
// ---------------------------------------------------------------------------
__device__ float g_T [NTOK*DD];
__device__ float g_Y [NTOK*DD];
__device__ float g_Z [NTOK*DD];
__device__ hf g_Xh [NTOK*DD];
__device__ hf g_Xl [NTOK*DD];
__device__ hf g_Eh [NTOK*DD];
__device__ hf g_El [NTOK*DD];
__device__ hf g_Yh [NTOK*DD];
__device__ hf g_Yl [NTOK*DD];
__device__ hf g_Zh [NTOK*DD];
__device__ hf g_Zl [NTOK*DD];
__device__ hf g_AOh[NTOK*DD];
__device__ hf g_AOl[NTOK*DD];
__device__ hf g_Qh [NTOK*DD];
__device__ hf g_Ql [NTOK*DD];
__device__ hf g_Kh [NTOK*DD];
__device__ hf g_Kl [NTOK*DD];
__device__ hf g_Vh [NTOK*DD];
__device__ hf g_Vl [NTOK*DD];
__device__ hf g_Hh [NTOK*FFN];
__device__ hf g_Hl [NTOK*FFN];
__device__ hf g_Wh [8*DD*DD];
__device__ hf g_Wl [8*DD*DD];
__device__ hf g_W1h[FFN*DD];
__device__ hf g_W1l[FFN*DD];
__device__ hf g_W2h[DD*FFN];
__device__ hf g_W2l[DD*FFN];

// ---------------------------------------------------------------------------
// PTX helpers
// ---------------------------------------------------------------------------
__device__ __forceinline__ uint32_t sptr(const void* p)
{
    return (uint32_t)__cvta_generic_to_shared(p);
}

__device__ __forceinline__ void ldsm_x4(uint32_t& r0, uint32_t& r1,
                                        uint32_t& r2, uint32_t& r3, uint32_t addr)
{
    asm volatile("ldmatrix.sync.aligned.m8n8.x4.shared.b16 {%0,%1,%2,%3}, [%4];"
                 : "=r"(r0), "=r"(r1), "=r"(r2), "=r"(r3) : "r"(addr));
}

__device__ __forceinline__ void ldsm_x4_t(uint32_t& r0, uint32_t& r1,
                                          uint32_t& r2, uint32_t& r3, uint32_t addr)
{
    asm volatile("ldmatrix.sync.aligned.m8n8.x4.trans.shared.b16 {%0,%1,%2,%3}, [%4];"
                 : "=r"(r0), "=r"(r1), "=r"(r2), "=r"(r3) : "r"(addr));
}

// fp16 inputs, fp32 accumulate
__device__ __forceinline__ void mma_f16(float* c, const uint32_t* a, const uint32_t* b)
{
    asm volatile("mma.sync.aligned.m16n8k16.row.col.f32.f16.f16.f32 "
                 "{%0,%1,%2,%3}, {%4,%5,%6,%7}, {%8,%9}, {%0,%1,%2,%3};"
                 : "+f"(c[0]), "+f"(c[1]), "+f"(c[2]), "+f"(c[3])
                 : "r"(a[0]), "r"(a[1]), "r"(a[2]), "r"(a[3]),
                   "r"(b[0]), "r"(b[1]));
}

// fp16 inputs, fp16 accumulate (used only for lo-correction passes)
__device__ __forceinline__ void mma_f16acc(uint32_t* c, const uint32_t* a, const uint32_t* b)
{
    asm volatile("mma.sync.aligned.m16n8k16.row.col.f16.f16.f16.f16 "
                 "{%0,%1}, {%2,%3,%4,%5}, {%6,%7}, {%0,%1};"
                 : "+r"(c[0]), "+r"(c[1])
                 : "r"(a[0]), "r"(a[1]), "r"(a[2]), "r"(a[3]),
                   "r"(b[0]), "r"(b[1]));
}

__device__ __forceinline__ void cp_async16(uint32_t saddr, const void* gaddr)
{
    asm volatile("cp.async.cg.shared.global [%0], [%1], 16;" :: "r"(saddr), "l"(gaddr));
}
__device__ __forceinline__ void cp_commit()
{
    asm volatile("cp.async.commit_group;");
}
template<int N>
__device__ __forceinline__ void cp_wait()
{
    asm volatile("cp.async.wait_group %0;" :: "n"(N));
}

__device__ __forceinline__ void split1(float v, hf& h, hf& l)
{
    h = __float2half_rn(v);
    l = __float2half_rn(v - __half2float(h));
}

__device__ __forceinline__ uint32_t pack_split_hi(float a, float b)
{
    hf2 p = __halves2half2(__float2half_rn(a), __float2half_rn(b));
    return *(uint32_t*)&p;
}
__device__ __forceinline__ uint32_t pack_split_lo(float a, float b)
{
    hf ha = __float2half_rn(a), hb = __float2half_rn(b);
    hf2 p = __halves2half2(__float2half_rn(a - __half2float(ha)),
                           __float2half_rn(b - __half2float(hb)));
    return *(uint32_t*)&p;
}

// e^x for x <= 0, FMA-pipe polynomial (no MUFU). ~3e-8 rel err.
__device__ __forceinline__ float fexp(float x)
{
    float t = fmaxf(x * 1.44269504089f, -126.0f);
    float fn = t + 12582912.0f;            // 1.5*2^23: round-to-nearest int
    float n  = fn - 12582912.0f;
    float f  = t - n;
    float p = 1.54035304e-4f;
    p = fmaf(p, f, 1.33335581e-3f);
    p = fmaf(p, f, 9.61812910e-3f);
    p = fmaf(p, f, 5.55041087e-2f);
    p = fmaf(p, f, 2.40226507e-1f);
    p = fmaf(p, f, 6.93147182e-1f);
    p = fmaf(p, f, 1.0f);
    return p * __int_as_float(((int)n + 127) << 23);
}

// ---------------------------------------------------------------------------
// split_kernel: fp32 x -> fp16 hi/lo, float4-vectorized
// ---------------------------------------------------------------------------
__global__ __launch_bounds__(256)
void split_kernel(const float* __restrict__ x, hf* __restrict__ h,
                  hf* __restrict__ l, int n4)
{
    int i = blockIdx.x * 256 + threadIdx.x;
    if (i >= n4) return;
    float4 v = ((const float4*)x)[i];
    ((uint32_t*)h)[i * 2]     = pack_split_hi(v.x, v.y);
    ((uint32_t*)h)[i * 2 + 1] = pack_split_hi(v.z, v.w);
    ((uint32_t*)l)[i * 2]     = pack_split_lo(v.x, v.y);
    ((uint32_t*)l)[i * 2 + 1] = pack_split_lo(v.z, v.w);
}

// ---------------------------------------------------------------------------
// fp16-split tensor-core GEMM (mma.sync), pre-split operands.
//   C[M,N] = A[M,K]*B[N,K]^T
// NPASS=3: AhBh(f32acc) + AlBh(f16acc) + AhBl(f16acc)   (~1e-6 rel)
// NPASS=2: AhBh(f32acc) + AlBh(f16acc)                  (~1e-4 rel; B lo unused)
// BM=BN=128, BK=64, 512 threads (16 warps 4x4), warp tile 32x32.
// 2-stage cp.async; 128B swizzled rows. EPI: 0 none, 1 +bias+LReLU, 2 +bias.
// OUT: 0 fp32 C, 1 split fp16 Ch/Cl.
// ---------------------------------------------------------------------------
template<int EPI, int OUT, int NPASS>
__global__ __launch_bounds__(512)
void bgemm3(const hf* __restrict__ Ahg, const hf* __restrict__ Alg,
            const hf* __restrict__ Bhg, const hf* __restrict__ Blg,
            const float* __restrict__ bias,
            float* __restrict__ C, hf* __restrict__ Ch, hf* __restrict__ Cl,
            int M, int N, int K)
{
    extern __shared__ __align__(16) uint8_t smp[];
    constexpr uint32_t TILEB  = 128 * 64 * 2;   // 16KB per tile
    constexpr uint32_t STAGEB = 4 * TILEB;      // Ah, Al, Bh, Bl slots

    const int bm   = blockIdx.y * 128;
    const int bn   = blockIdx.x * 128;
    const int tid  = threadIdx.x;
    const int lane = tid & 31;
    const int wid  = tid >> 5;
    const int wm   = wid >> 2;   // 0..3
    const int wn   = wid & 3;    // 0..3
    const uint32_t smbase = sptr(smp);

    float acc[2][4][4];
    uint32_t acch[2][4][2];      // fp16 accumulators for lo passes
    #pragma unroll
    for (int i = 0; i < 2; i++)
        #pragma unroll
        for (int j = 0; j < 4; j++) {
            #pragma unroll
            for (int t = 0; t < 4; t++) acc[i][j][t] = 0.f;
            acch[i][j][0] = 0u; acch[i][j][1] = 0u;
        }

    const int arow = ((lane >> 3) & 1) * 8 + (lane & 7);
    const int acol = ((lane >> 4) & 1) * 8;
    const int brow = ((lane >> 4) & 1) * 8 + (lane & 7);
    const int bcol = ((lane >> 3) & 1) * 8;

    auto load_stage = [&](int s, int k0) {
        const uint32_t base = smbase + (uint32_t)s * STAGEB;
        #pragma unroll
        for (int t = 0; t < 2; t++) {
            int idx = tid + t * 512;          // 0..1023 chunks per tile
            int row = idx >> 3, c = idx & 7;
            uint32_t boff = (uint32_t)row * 128 + ((uint32_t)(c ^ (row & 7)) << 4);
            const size_t ga = (size_t)(bm + row) * K + k0 + c * 8;
            const size_t gb = (size_t)(bn + row) * K + k0 + c * 8;
            cp_async16(base + boff,             Ahg + ga);
            cp_async16(base + TILEB + boff,     Alg + ga);
            cp_async16(base + 2 * TILEB + boff, Bhg + gb);
            if (NPASS == 3)
                cp_async16(base + 3 * TILEB + boff, Blg + gb);
        }
    };

    auto compute_stage = [&](int s) {
        const uint32_t base = smbase + (uint32_t)s * STAGEB;
        #pragma unroll
        for (int kk = 0; kk < 64; kk += 16) {
            uint32_t ah[2][4], al[2][4], bh[4][2], bl[4][2];
            #pragma unroll
            for (int mf = 0; mf < 2; mf++) {
                int r = wm * 32 + mf * 16 + arow;
                int c = (kk + acol) >> 3;
                uint32_t off = (uint32_t)r * 128 + ((uint32_t)(c ^ (r & 7)) << 4);
                ldsm_x4(ah[mf][0], ah[mf][1], ah[mf][2], ah[mf][3], base + off);
                ldsm_x4(al[mf][0], al[mf][1], al[mf][2], al[mf][3], base + TILEB + off);
            }
            #pragma unroll
            for (int p = 0; p < 2; p++) {
                int n = wn * 32 + p * 16 + brow;
                int c = (kk + bcol) >> 3;
                uint32_t off = (uint32_t)n * 128 + ((uint32_t)(c ^ (n & 7)) << 4);
                uint32_t t0, t1, t2, t3;
                ldsm_x4(t0, t1, t2, t3, base + 2 * TILEB + off);
                bh[2 * p][0] = t0; bh[2 * p][1] = t1;
                bh[2 * p + 1][0] = t2; bh[2 * p + 1][1] = t3;
                if (NPASS == 3) {
                    ldsm_x4(t0, t1, t2, t3, base + 3 * TILEB + off);
                    bl[2 * p][0] = t0; bl[2 * p][1] = t1;
                    bl[2 * p + 1][0] = t2; bl[2 * p + 1][1] = t3;
                }
            }
            #pragma unroll
            for (int mf = 0; mf < 2; mf++)
                #pragma unroll
                for (int nf = 0; nf < 4; nf++) {
                    mma_f16(acc[mf][nf], ah[mf], bh[nf]);
                    mma_f16acc(acch[mf][nf], al[mf], bh[nf]);
                    if (NPASS == 3)
                        mma_f16acc(acch[mf][nf], ah[mf], bl[nf]);
                }
        }
    };

    const int nk = K >> 6;
    load_stage(0, 0);
    cp_commit();
    for (int ch = 0; ch < nk; ch++) {
        if (ch + 1 < nk) {
            load_stage((ch + 1) & 1, (ch + 1) << 6);
            cp_commit();
            cp_wait<1>();
        } else {
            cp_wait<0>();
        }
        __syncthreads();
        compute_stage(ch & 1);
        __syncthreads();
    }

    // epilogue: combine fp32 + fp16 accumulators
    const int r0  = lane >> 2;
    const int cc0 = (lane & 3) * 2;
    #pragma unroll
    for (int mf = 0; mf < 2; mf++) {
        #pragma unroll
        for (int nf = 0; nf < 4; nf++) {
            int row = bm + wm * 32 + mf * 16 + r0;
            int col = bn + wn * 32 + nf * 8 + cc0;
            float2 lo0 = __half22float2(*(hf2*)&acch[mf][nf][0]);
            float2 lo1 = __half22float2(*(hf2*)&acch[mf][nf][1]);
            float2 v0 = make_float2(acc[mf][nf][0] + lo0.x, acc[mf][nf][1] + lo0.y);
            float2 v1 = make_float2(acc[mf][nf][2] + lo1.x, acc[mf][nf][3] + lo1.y);
            if (EPI) {
                float b0 = bias[col], b1 = bias[col + 1];
                v0.x += b0; v0.y += b1; v1.x += b0; v1.y += b1;
                if (EPI == 1) {
                    v0.x = v0.x > 0.f ? v0.x : 0.01f * v0.x;
                    v0.y = v0.y > 0.f ? v0.y : 0.01f * v0.y;
                    v1.x = v1.x > 0.f ? v1.x : 0.01f * v1.x;
                    v1.y = v1.y > 0.f ? v1.y : 0.01f * v1.y;
                }
            }
            if (OUT == 0) {
                *(float2*)(C + (size_t)row * N + col)       = v0;
                *(float2*)(C + (size_t)(row + 8) * N + col) = v1;
            } else {
                *(uint32_t*)(Ch + (size_t)row * N + col)       = pack_split_hi(v0.x, v0.y);
                *(uint32_t*)(Cl + (size_t)row * N + col)       = pack_split_lo(v0.x, v0.y);
                *(uint32_t*)(Ch + (size_t)(row + 8) * N + col) = pack_split_hi(v1.x, v1.y);
                *(uint32_t*)(Cl + (size_t)(row + 8) * N + col) = pack_split_lo(v1.x, v1.y);
            }
        }
    }
}

// ---------------------------------------------------------------------------
// FA2-style attention on tensor cores (fp16x3 S and PV), poly-exp softmax.
// CTA = (b, h, 64-query tile), 128 threads (4 warps x 16 q-rows).
// Q/K/V pre-split fp16 hi/lo, [tok][512], head at cols h*64..h*64+63.
// Dynamic smem 48KB: Qh,Ql,Kh,Kl,Vh,Vl tiles (64x64 each, 128B swizzled rows).
// ---------------------------------------------------------------------------
__global__ __launch_bounds__(128)
void attn_tc(const hf* __restrict__ Qhg, const hf* __restrict__ Qlg,
             const hf* __restrict__ Khg, const hf* __restrict__ Klg,
             const hf* __restrict__ Vhg, const hf* __restrict__ Vlg,
             const int* __restrict__ vlen, int per_query,
             hf* __restrict__ Oh, hf* __restrict__ Ol)
{
    extern __shared__ __align__(16) uint8_t smp[];
    __shared__ int s_red[4];
    constexpr uint32_t OQH = 0, OQL = 8192, OKH = 16384, OKL = 24576;
    constexpr uint32_t OVH = 32768, OVL = 40960;

    const int b  = blockIdx.z;
    const int h  = blockIdx.y;
    const int q0 = blockIdx.x * 64;
    const int tid  = threadIdx.x;
    const int lane = tid & 31;
    const int w    = tid >> 5;
    const uint32_t smbase = sptr(smp);
    const size_t rowbase = ((size_t)b * TT) * DD + h * DH;

    const int arow = ((lane >> 3) & 1) * 8 + (lane & 7);
    const int acol = ((lane >> 4) & 1) * 8;
    const int brow = ((lane >> 4) & 1) * 8 + (lane & 7);
    const int bcol = ((lane >> 3) & 1) * 8;

    auto ldtile = [&](uint32_t dst, const hf* src, int row0) {
        #pragma unroll
        for (int t = 0; t < 4; t++) {
            int idx = tid + t * 128;          // 0..511
            int row = idx >> 3, c = idx & 7;
            uint32_t boff = dst + (uint32_t)row * 128 + ((uint32_t)(c ^ (row & 7)) << 4);
            cp_async16(smbase + boff, src + rowbase + (size_t)(row0 + row) * DD + c * 8);
        }
    };

    ldtile(OQH, Qhg, q0);
    ldtile(OQL, Qlg, q0);
    cp_commit();

    const int r0g = q0 + w * 16 + (lane >> 2);
    const int vl0 = per_query ? vlen[b * TT + r0g]     : vlen[b];
    const int vl1 = per_query ? vlen[b * TT + r0g + 8] : vlen[b];

    int v = per_query ? ((tid < 64) ? vlen[b * TT + q0 + tid] : 1) : vlen[b];
    #pragma unroll
    for (int off = 16; off; off >>= 1) v = max(v, __shfl_xor_sync(0xffffffffu, v, off));
    if (lane == 0) s_red[w] = v;

    cp_wait<0>();
    __syncthreads();
    const int maxvl = max(max(s_red[0], s_red[1]), max(s_red[2], s_red[3]));

    uint32_t qh[4][4], ql[4][4];
    #pragma unroll
    for (int kf = 0; kf < 4; kf++) {
        int r = w * 16 + arow;
        int c = (kf * 16 + acol) >> 3;
        uint32_t off = (uint32_t)r * 128 + ((uint32_t)(c ^ (r & 7)) << 4);
        ldsm_x4(qh[kf][0], qh[kf][1], qh[kf][2], qh[kf][3], smbase + OQH + off);
        ldsm_x4(ql[kf][0], ql[kf][1], ql[kf][2], ql[kf][3], smbase + OQL + off);
    }

    float m0 = -1e30f, m1 = -1e30f, l0 = 0.f, l1 = 0.f;
    float o[8][4];
    #pragma unroll
    for (int i = 0; i < 8; i++)
        #pragma unroll
        for (int j = 0; j < 4; j++) o[i][j] = 0.f;

    const int ktiles = (maxvl + 63) >> 6;

    for (int kt = 0; kt < ktiles; kt++) {
        __syncthreads();
        ldtile(OKH, Khg, kt * 64);
        ldtile(OKL, Klg, kt * 64);
        ldtile(OVH, Vhg, kt * 64);
        ldtile(OVL, Vlg, kt * 64);
        cp_commit();
        cp_wait<0>();
        __syncthreads();

        // ---- S = Q K^T (fp16x3) ----
        float s[8][4];
        #pragma unroll
        for (int i = 0; i < 8; i++)
            #pragma unroll
            for (int j = 0; j < 4; j++) s[i][j] = 0.f;

        #pragma unroll
        for (int kf = 0; kf < 4; kf++) {
            uint32_t bh[8][2], bl[8][2];
            #pragma unroll
            for (int p = 0; p < 4; p++) {
                int n = p * 16 + brow;
                int c = (kf * 16 + bcol) >> 3;
                uint32_t off = (uint32_t)n * 128 + ((uint32_t)(c ^ (n & 7)) << 4);
                uint32_t t0, t1, t2, t3;
                ldsm_x4(t0, t1, t2, t3, smbase + OKH + off);
                bh[2 * p][0] = t0; bh[2 * p][1] = t1;
                bh[2 * p + 1][0] = t2; bh[2 * p + 1][1] = t3;
                ldsm_x4(t0, t1, t2, t3, smbase + OKL + off);
                bl[2 * p][0] = t0; bl[2 * p][1] = t1;
                bl[2 * p + 1][0] = t2; bl[2 * p + 1][1] = t3;
            }
            #pragma unroll
            for (int nf = 0; nf < 8; nf++) {
                mma_f16(s[nf], qh[kf], bh[nf]);
                mma_f16(s[nf], qh[kf], bl[nf]);
                mma_f16(s[nf], ql[kf], bh[nf]);
            }
        }

        // ---- scale + mask ----
        const int kbase = kt * 64 + (lane & 3) * 2;
        #pragma unroll
        for (int nf = 0; nf < 8; nf++) {
            int k0c = kbase + nf * 8;
            s[nf][0] = (k0c     < vl0) ? s[nf][0] * 0.125f : -1e10f;
            s[nf][1] = (k0c + 1 < vl0) ? s[nf][1] * 0.125f : -1e10f;
            s[nf][2] = (k0c     < vl1) ? s[nf][2] * 0.125f : -1e10f;
            s[nf][3] = (k0c + 1 < vl1) ? s[nf][3] * 0.125f : -1e10f;
        }

        // ---- row max ----
        float rm0 = -1e30f, rm1 = -1e30f;
        #pragma unroll
        for (int nf = 0; nf < 8; nf++) {
            rm0 = fmaxf(rm0, fmaxf(s[nf][0], s[nf][1]));
            rm1 = fmaxf(rm1, fmaxf(s[nf][2], s[nf][3]));
        }
        rm0 = fmaxf(rm0, __shfl_xor_sync(0xffffffffu, rm0, 1));
        rm0 = fmaxf(rm0, __shfl_xor_sync(0xffffffffu, rm0, 2));
        rm1 = fmaxf(rm1, __shfl_xor_sync(0xffffffffu, rm1, 1));
        rm1 = fmaxf(rm1, __shfl_xor_sync(0xffffffffu, rm1, 2));

        const float mn0 = fmaxf(m0, rm0), mn1 = fmaxf(m1, rm1);
        const float al0 = fexp(m0 - mn0), al1 = fexp(m1 - mn1);
        m0 = mn0; m1 = mn1;

        // ---- exp + pack P (split hi/lo) ----
        float ps0 = 0.f, ps1 = 0.f;
        uint32_t phi[4][4], plo[4][4];
        #pragma unroll
        for (int nf = 0; nf < 8; nf++) {
            float p0 = fexp(s[nf][0] - mn0);
            float p1 = fexp(s[nf][1] - mn0);
            float p2 = fexp(s[nf][2] - mn1);
            float p3 = fexp(s[nf][3] - mn1);
            ps0 += p0 + p1; ps1 += p2 + p3;
            int kf = nf >> 1, half = nf & 1;
            phi[kf][2 * half]     = pack_split_hi(p0, p1);
            phi[kf][2 * half + 1] = pack_split_hi(p2, p3);
            plo[kf][2 * half]     = pack_split_lo(p0, p1);
            plo[kf][2 * half + 1] = pack_split_lo(p2, p3);
        }
        ps0 += __shfl_xor_sync(0xffffffffu, ps0, 1);
        ps0 += __shfl_xor_sync(0xffffffffu, ps0, 2);
        ps1 += __shfl_xor_sync(0xffffffffu, ps1, 1);
        ps1 += __shfl_xor_sync(0xffffffffu, ps1, 2);
        l0 = l0 * al0 + ps0;
        l1 = l1 * al1 + ps1;

        #pragma unroll
        for (int nf = 0; nf < 8; nf++) {
            o[nf][0] *= al0; o[nf][1] *= al0;
            o[nf][2] *= al1; o[nf][3] *= al1;
        }

        // ---- O += P V (fp16x3), V via ldmatrix.trans ----
        const int tq = lane >> 3, rq = lane & 7;
        #pragma unroll
        for (int df2 = 0; df2 < 4; df2++) {
            uint32_t vh[4][4], vl_[4][4];
            #pragma unroll
            for (int kf = 0; kf < 4; kf++) {
                int krow = kf * 16 + (tq & 1) * 8 + rq;
                int c = df2 * 2 + (tq >> 1);
                uint32_t off = (uint32_t)krow * 128 + ((uint32_t)(c ^ (krow & 7)) << 4);
                ldsm_x4_t(vh[kf][0], vh[kf][1], vh[kf][2], vh[kf][3], smbase + OVH + off);
                ldsm_x4_t(vl_[kf][0], vl_[kf][1], vl_[kf][2], vl_[kf][3], smbase + OVL + off);
            }
            #pragma unroll
            for (int kf = 0; kf < 4; kf++) {
                mma_f16(o[2 * df2],     phi[kf], &vh[kf][0]);
                mma_f16(o[2 * df2 + 1], phi[kf], &vh[kf][2]);
                mma_f16(o[2 * df2],     phi[kf], &vl_[kf][0]);
                mma_f16(o[2 * df2 + 1], phi[kf], &vl_[kf][2]);
                mma_f16(o[2 * df2],     plo[kf], &vh[kf][0]);
                mma_f16(o[2 * df2 + 1], plo[kf], &vh[kf][2]);
            }
        }
    }

    // ---- normalize + write split output ----
    const float inv0 = 1.f / l0, inv1 = 1.f / l1;
    const size_t rA = rowbase + (size_t)r0g * DD;
    const size_t rB = rowbase + (size_t)(r0g + 8) * DD;
    const int c0 = (lane & 3) * 2;
    #pragma unroll
    for (int nf = 0; nf < 8; nf++) {
        int col = nf * 8 + c0;
        float a0 = o[nf][0] * inv0, a1 = o[nf][1] * inv0;
        float b0 = o[nf][2] * inv1, b1 = o[nf][3] * inv1;
        *(uint32_t*)(Oh + rA + col) = pack_split_hi(a0, a1);
        *(uint32_t*)(Ol + rA + col) = pack_split_lo(a0, a1);
        *(uint32_t*)(Oh + rB + col) = pack_split_hi(b0, b1);
        *(uint32_t*)(Ol + rB + col) = pack_split_lo(b0, b1);
    }
}

// ---------------------------------------------------------------------------
// out[row] = LayerNorm(x[row] + y[row]) * gamma + beta, D=512.
// SPLIT=1: also write fp16 hi/lo of the result.
// ---------------------------------------------------------------------------
template<int SPLIT>
__global__ __launch_bounds__(128)
void add_ln_kernel(const float* __restrict__ x, const float* __restrict__ y,
                   const float* __restrict__ g, const float* __restrict__ be,
                   float* __restrict__ out, hf* __restrict__ oh,
                   hf* __restrict__ ol)
{
    __shared__ float ws[4], ws2[4];
    const int row = blockIdx.x;
    const int tid = threadIdx.x;

    float4 xv = ((const float4*)(x + (size_t)row * DD))[tid];
    float4 yv = ((const float4*)(y + (size_t)row * DD))[tid];
    float4 v;
    v.x = xv.x + yv.x; v.y = xv.y + yv.y; v.z = xv.z + yv.z; v.w = xv.w + yv.w;

    float s  = v.x + v.y + v.z + v.w;
    float s2 = v.x * v.x + v.y * v.y + v.z * v.z + v.w * v.w;
    #pragma unroll
    for (int off = 16; off; off >>= 1) {
        s  += __shfl_xor_sync(0xffffffffu, s,  off);
        s2 += __shfl_xor_sync(0xffffffffu, s2, off);
    }
    if ((tid & 31) == 0) { ws[tid >> 5] = s; ws2[tid >> 5] = s2; }
    __syncthreads();
    s  = ws[0]  + ws[1]  + ws[2]  + ws[3];
    s2 = ws2[0] + ws2[1] + ws2[2] + ws2[3];

    const float mean = s * (1.f / DD);
    const float var  = s2 * (1.f / DD) - mean * mean;
    const float r    = rsqrtf(var + 1e-5f);

    float4 gv = ((const float4*)g)[tid];
    float4 bv = ((const float4*)be)[tid];
    float4 w;
    w.x = (v.x - mean) * r * gv.x + bv.x;
    w.y = (v.y - mean) * r * gv.y + bv.y;
    w.z = (v.z - mean) * r * gv.z + bv.z;
    w.w = (v.w - mean) * r * gv.w + bv.w;
    ((float4*)(out + (size_t)row * DD))[tid] = w;

    if (SPLIT) {
        size_t o4 = (size_t)row * DD + tid * 4;
        *(uint32_t*)(oh + o4)     = pack_split_hi(w.x, w.y);
        *(uint32_t*)(oh + o4 + 2) = pack_split_hi(w.z, w.w);
        *(uint32_t*)(ol + o4)     = pack_split_lo(w.x, w.y);
        *(uint32_t*)(ol + o4 + 2) = pack_split_lo(w.z, w.w);
    }
}

// ---------------------------------------------------------------------------
// Host driver
// ---------------------------------------------------------------------------
template<typename T>
static T* symaddr(const void* sym)
{
    void* p = nullptr;
    cudaGetSymbolAddress(&p, sym);
    return (T*)p;
}

extern "C" void kernel_launch(void* const* d_in, const int* in_sizes, int n_in,
                              void* d_out, int out_size)
{
    (void)in_sizes; (void)n_in; (void)out_size;

    const float* X    = (const float*)d_in[0];
    const float* enc  = (const float*)d_in[1];
    const int*   dvl  = (const int*)d_in[2];
    const int*   evl  = (const int*)d_in[3];
    const float* Wmat[8];
    for (int i = 0; i < 8; i++) Wmat[i] = (const float*)d_in[4 + i];
    const float* W1   = (const float*)d_in[12];
    const float* b1   = (const float*)d_in[13];
    const float* W2   = (const float*)d_in[14];
    const float* b2   = (const float*)d_in[15];
    const float* g1   = (const float*)d_in[16];
    const float* be1  = (const float*)d_in[17];
    const float* g2   = (const float*)d_in[18];
    const float* be2  = (const float*)d_in[19];
    const float* g3   = (const float*)d_in[20];
    const float* be3  = (const float*)d_in[21];
    float* out = (float*)d_out;

    float* Tb = symaddr<float>(g_T);
    float* Yb = symaddr<float>(g_Y);
    float* Zb = symaddr<float>(g_Z);
    hf* Xh = symaddr<hf>(g_Xh);   hf* Xl = symaddr<hf>(g_Xl);
    hf* Eh = symaddr<hf>(g_Eh);   hf* El = symaddr<hf>(g_El);
    hf* Yh = symaddr<hf>(g_Yh);   hf* Yl = symaddr<hf>(g_Yl);
    hf* Zh = symaddr<hf>(g_Zh);   hf* Zl = symaddr<hf>(g_Zl);
    hf* AOh = symaddr<hf>(g_AOh); hf* AOl = symaddr<hf>(g_AOl);
    hf* Qh = symaddr<hf>(g_Qh);   hf* Ql = symaddr<hf>(g_Ql);
    hf* Kh = symaddr<hf>(g_Kh);   hf* Kl = symaddr<hf>(g_Kl);
    hf* Vh = symaddr<hf>(g_Vh);   hf* Vl = symaddr<hf>(g_Vl);
    hf* Hh = symaddr<hf>(g_Hh);   hf* Hl = symaddr<hf>(g_Hl);
    hf* Wh = symaddr<hf>(g_Wh);   hf* Wl = symaddr<hf>(g_Wl);
    hf* W1h = symaddr<hf>(g_W1h); hf* W1l = symaddr<hf>(g_W1l);
    hf* W2h = symaddr<hf>(g_W2h); hf* W2l = symaddr<hf>(g_W2l);

    const int GSMEM = 2 * 4 * 128 * 64 * 2;   // 128KB
    const int ASMEM = 6 * 64 * 64 * 2;        // 48KB
    cudaFuncSetAttribute(bgemm3<0, 1, 3>, cudaFuncAttributeMaxDynamicSharedMemorySize, GSMEM);
    cudaFuncSetAttribute(bgemm3<0, 0, 3>, cudaFuncAttributeMaxDynamicSharedMemorySize, GSMEM);
    cudaFuncSetAttribute(bgemm3<0, 0, 2>, cudaFuncAttributeMaxDynamicSharedMemorySize, GSMEM);
    cudaFuncSetAttribute(bgemm3<1, 1, 2>, cudaFuncAttributeMaxDynamicSharedMemorySize, GSMEM);
    cudaFuncSetAttribute(bgemm3<2, 0, 2>, cudaFuncAttributeMaxDynamicSharedMemorySize, GSMEM);
    cudaFuncSetAttribute(attn_tc, cudaFuncAttributeMaxDynamicSharedMemorySize, ASMEM);

    const int M = NTOK;
    dim3 gD(DD / 128, M / 128);     // N=512 GEMMs
    dim3 gF(FFN / 128, M / 128);    // N=2048 GEMM
    dim3 gA(TT / 64, HH, BB);       // attention

    // ---- splits (inputs + weights) ----
    split_kernel<<<(NTOK * DD / 4 + 255) / 256, 256>>>(X,   Xh, Xl, NTOK * DD / 4);
    split_kernel<<<(NTOK * DD / 4 + 255) / 256, 256>>>(enc, Eh, El, NTOK * DD / 4);
    for (int i = 0; i < 8; i++)
        split_kernel<<<(DD * DD / 4 + 255) / 256, 256>>>(Wmat[i],
            Wh + (size_t)i * DD * DD, Wl + (size_t)i * DD * DD, DD * DD / 4);
    split_kernel<<<(FFN * DD / 4 + 255) / 256, 256>>>(W1, W1h, W1l, FFN * DD / 4);
    split_kernel<<<(DD * FFN / 4 + 255) / 256, 256>>>(W2, W2h, W2l, DD * FFN / 4);

    const size_t WD = (size_t)DD * DD;

    // ---- self-attention (everything feeding scores: 3-pass) ----
    bgemm3<0, 1, 3><<<gD, 512, GSMEM>>>(Xh, Xl, Wh + 0 * WD, Wl + 0 * WD, nullptr, nullptr, Qh, Ql, M, DD, DD);
    bgemm3<0, 1, 3><<<gD, 512, GSMEM>>>(Xh, Xl, Wh + 1 * WD, Wl + 1 * WD, nullptr, nullptr, Kh, Kl, M, DD, DD);
    bgemm3<0, 1, 3><<<gD, 512, GSMEM>>>(Xh, Xl, Wh + 2 * WD, Wl + 2 * WD, nullptr, nullptr, Vh, Vl, M, DD, DD);
    attn_tc<<<gA, 128, ASMEM>>>(Qh, Ql, Kh, Kl, Vh, Vl, dvl, 1, AOh, AOl);
    bgemm3<0, 0, 3><<<gD, 512, GSMEM>>>(AOh, AOl, Wh + 3 * WD, Wl + 3 * WD, nullptr, Tb, nullptr, nullptr, M, DD, DD);
    add_ln_kernel<1><<<M, 128>>>(X, Tb, g1, be1, Yb, Yh, Yl);

    // ---- cross-attention ----
    bgemm3<0, 1, 3><<<gD, 512, GSMEM>>>(Yh, Yl, Wh + 4 * WD, Wl + 4 * WD, nullptr, nullptr, Qh, Ql, M, DD, DD);
    bgemm3<0, 1, 3><<<gD, 512, GSMEM>>>(Eh, El, Wh + 5 * WD, Wl + 5 * WD, nullptr, nullptr, Kh, Kl, M, DD, DD);
    bgemm3<0, 1, 3><<<gD, 512, GSMEM>>>(Eh, El, Wh + 6 * WD, Wl + 6 * WD, nullptr, nullptr, Vh, Vl, M, DD, DD);
    attn_tc<<<gA, 128, ASMEM>>>(Qh, Ql, Kh, Kl, Vh, Vl, evl, 0, AOh, AOl);
    // ---- no softmax downstream of here: 2-pass ----
    bgemm3<0, 0, 2><<<gD, 512, GSMEM>>>(AOh, AOl, Wh + 7 * WD, Wl + 7 * WD, nullptr, Tb, nullptr, nullptr, M, DD, DD);
    add_ln_kernel<1><<<M, 128>>>(Yb, Tb, g2, be2, Zb, Zh, Zl);

    // ---- FFN (2-pass) ----
    bgemm3<1, 1, 2><<<gF, 512, GSMEM>>>(Zh, Zl, W1h, W1l, b1, nullptr, Hh, Hl, M, FFN, DD);
    bgemm3<2, 0, 2><<<gD, 512, GSMEM>>>(Hh, Hl, W2h, W2l, b2, Tb, nullptr, nullptr, M, DD, FFN);
    add_ln_kernel<0><<<M, 128>>>(Zb, Tb, g3, be3, out, nullptr, nullptr);
}